// round 14
// baseline (speedup 1.0000x reference)
#include <cuda_runtime.h>
#include <cuda_fp16.h>
#include <math.h>
#include <stdint.h>

// ---------------- problem constants ----------------
#define Bsz    64
#define Dm     768
#define Hn     12
#define DHd    64
#define Lnum   12
#define FFd    3072
#define NPRn   8
#define STOK   205
#define NPATCH 196
#define MTOK   (Bsz*STOK)     // 13120
#define MPATCH (Bsz*NPATCH)   // 12544 = 98*128
#define MPAD   13184          // 103*128 >= MTOK
#define NQKV   2304           // fused q|k|v output width

// ---------------- static device scratch ----------------
__device__ float  g_x[MPAD*Dm];
__device__ float  g_feat[MPATCH*Dm];              // conv output fp32
__device__ __half g_qkvh[(size_t)MPAD*NQKV];      // packed q|k|v fp16
__device__ float  g_bqkv[(size_t)Lnum*NQKV];
__device__ __half g_ae1[(size_t)MPAD*Dm];         // fp16 activations (K=768 GEMMs)
__device__ __half g_ae2[(size_t)MPAD*FFd];        // fp16 MLP hidden
__device__ __half g_wqkv[(size_t)Lnum*NQKV*Dm];
__device__ __half g_wo[(size_t)Lnum*Dm*Dm];
__device__ __half g_w1[(size_t)Lnum*FFd*Dm];
__device__ __half g_w2[(size_t)Lnum*Dm*FFd];
__device__ __half g_wp[(size_t)Dm*Dm];

// ---------------- helpers ----------------
__device__ __forceinline__ float qgelu(float x) {
    return x / (1.f + expf(-1.702f * x));
}
__device__ __forceinline__ void cp16(void* s, const void* g) {
    unsigned sa = (unsigned)__cvta_generic_to_shared(s);
    asm volatile("cp.async.ca.shared.global [%0], [%1], 16;\n" :: "r"(sa), "l"(g));
}
__device__ __forceinline__ void ldm4(unsigned* r, const __half* p) {
    unsigned s = (unsigned)__cvta_generic_to_shared(p);
    asm volatile("ldmatrix.sync.aligned.m8n8.x4.shared.b16 {%0,%1,%2,%3}, [%4];"
                 : "=r"(r[0]), "=r"(r[1]), "=r"(r[2]), "=r"(r[3]) : "r"(s));
}
__device__ __forceinline__ void mma16816(float* d, const unsigned* a, unsigned b0, unsigned b1) {
    asm volatile("mma.sync.aligned.m16n8k16.row.col.f32.f16.f16.f32 "
                 "{%0,%1,%2,%3}, {%4,%5,%6,%7}, {%8,%9}, {%0,%1,%2,%3};"
                 : "+f"(d[0]), "+f"(d[1]), "+f"(d[2]), "+f"(d[3])
                 : "r"(a[0]), "r"(a[1]), "r"(a[2]), "r"(a[3]), "r"(b0), "r"(b1));
}
__device__ __forceinline__ unsigned packh2(float a, float b) {
    __half2 h = __floats2half2_rn(a, b);
    return *(unsigned*)&h;
}

// ---------------- weight conversion: fp32 -> fp16 (vectorized x4) ----------------
__global__ __launch_bounds__(256) void wconv_kernel(const float* __restrict__ src,
                                                    __half* __restrict__ dst,
                                                    long long total4) {
    long long idx = (long long)blockIdx.x * 256 + threadIdx.x;
    if (idx >= total4) return;
    float4 v = ((const float4*)src)[idx];
    uint2 o;
    o.x = packh2(v.x, v.y);
    o.y = packh2(v.z, v.w);
    ((uint2*)dst)[idx] = o;
}

// ---------------- fused QKV weight conversion (scale folded into q rows, x4) -----------
__global__ __launch_bounds__(256) void wconv_qkv_kernel(const float* __restrict__ qw,
                                                        const float* __restrict__ kw,
                                                        const float* __restrict__ vw,
                                                        __half* __restrict__ dst) {
    long long idx = (long long)blockIdx.x * 256 + threadIdx.x;   // in float4 units
    if (idx >= (long long)Lnum * NQKV * (Dm / 4)) return;
    int k4 = (int)(idx % (Dm / 4));
    long long rowall = idx / (Dm / 4);
    int rr = (int)(rowall % NQKV);
    int l  = (int)(rowall / NQKV);
    float4 v;
    float sc = 1.f;
    if (rr < 768) {
        v = *(const float4*)(qw + (((size_t)l * Dm + rr) * Dm) + 4 * k4);
        sc = 0.125f;
    } else if (rr < 1536) {
        v = *(const float4*)(kw + (((size_t)l * Dm + (rr - 768)) * Dm) + 4 * k4);
    } else {
        v = *(const float4*)(vw + (((size_t)l * Dm + (rr - 1536)) * Dm) + 4 * k4);
    }
    uint2 o;
    o.x = packh2(v.x * sc, v.y * sc);
    o.y = packh2(v.z * sc, v.w * sc);
    ((uint2*)dst)[idx] = o;
}

__global__ __launch_bounds__(256) void bconv_qkv_kernel(const float* __restrict__ qb,
                                                        const float* __restrict__ kb,
                                                        const float* __restrict__ vb,
                                                        float* __restrict__ out) {
    int idx = blockIdx.x * 256 + threadIdx.x;
    if (idx >= Lnum * NQKV) return;
    int rr = idx % NQKV, l = idx / NQKV;
    float v;
    if (rr < 768)       v = qb[l * Dm + rr] * 0.125f;
    else if (rr < 1536) v = kb[l * Dm + (rr - 768)];
    else                v = vb[l * Dm + (rr - 1536)];
    out[idx] = v;
}

// ---------------- im2col fp16 (x2): image -> ae1 [MPATCH, 768] ----------------
__global__ __launch_bounds__(256) void im2col_kernel(const float* __restrict__ img,
                                                     __half* __restrict__ out) {
    int idx = blockIdx.x * 256 + threadIdx.x;     // in pairs
    if (idx >= MPATCH * Dm / 2) return;
    int k = (idx % (Dm / 2)) * 2;
    int m = idx / (Dm / 2);
    int b = m / NPATCH, p = m % NPATCH;
    int py = p / 14, px = p % 14;
    int c = k >> 8, i = (k >> 4) & 15, j = k & 15;
    float2 v = *(const float2*)(img + (((size_t)b * 3 + c) * 224 + (py * 16 + i)) * 224
                                + (px * 16 + j));
    ((unsigned*)out)[idx] = packh2(v.x, v.y);
}

// ---------------- assemble (x4) ----------------
__global__ __launch_bounds__(256) void assemble_kernel(const float* __restrict__ feat,
                                                       const float* __restrict__ cls,
                                                       const float* __restrict__ pos,
                                                       const float* __restrict__ gp,
                                                       float* __restrict__ x) {
    int idx = blockIdx.x * blockDim.x + threadIdx.x;   // in float4 units
    if (idx >= MTOK * Dm / 4) return;
    int d = (idx % (Dm / 4)) * 4;
    int s = (idx / (Dm / 4)) % STOK;
    int b = idx / ((Dm / 4) * STOK);
    float4 v;
    if (s == 0) {
        float4 cv = *(const float4*)(cls + d);
        float4 pv = *(const float4*)(pos + d);
        v = make_float4(cv.x + pv.x, cv.y + pv.y, cv.z + pv.z, cv.w + pv.w);
    } else if (s < 197) {
        float4 fv = *(const float4*)(feat + ((size_t)(b * NPATCH + s - 1)) * Dm + d);
        float4 pv = *(const float4*)(pos + (size_t)s * Dm + d);
        v = make_float4(fv.x + pv.x, fv.y + pv.y, fv.z + pv.z, fv.w + pv.w);
    } else {
        v = *(const float4*)(gp + (((size_t)b * Lnum + 0) * NPRn + (s - 197)) * Dm + d);
    }
    ((float4*)x)[idx] = v;
}

// ---------------- LayerNorm: one row per warp, 8 rows/block ----------------
// EXPOUT=0: fp32 out (out_stride). EXPOUT=1: fp16 out (stride 768).
// If gp != nullptr && layer>0: rows with s>=197 read the layer's prompt instead of x
// and write the raw prompt back into x (residual stream).
template <int EXPOUT>
__global__ __launch_bounds__(256) void ln_kernel(float* __restrict__ x,
                                                 const float* __restrict__ g,
                                                 const float* __restrict__ bb,
                                                 void* __restrict__ outp,
                                                 int in_stride, int out_stride,
                                                 const float* __restrict__ gp, int layer,
                                                 int nrows) {
    int warp = threadIdx.x >> 5, lane = threadIdx.x & 31;
    int row = blockIdx.x * 8 + warp;
    if (row >= nrows) return;
    const float* src = x + (size_t)row * in_stride;
    bool isPrompt = false;
    if (EXPOUT && gp != nullptr && layer > 0) {
        int s = row % STOK;
        if (s >= 197) {
            int b = row / STOK;
            src = gp + (((size_t)b * Lnum + layer) * NPRn + (s - 197)) * Dm;
            isPrompt = true;
        }
    }
    float4 v[6];
#pragma unroll
    for (int k = 0; k < 6; k++)
        v[k] = *(const float4*)(src + (k * 32 + lane) * 4);
    if (isPrompt) {
        float* xr = x + (size_t)row * in_stride;
#pragma unroll
        for (int k = 0; k < 6; k++)
            *(float4*)(xr + (k * 32 + lane) * 4) = v[k];
    }
    float s = 0.f, q = 0.f;
#pragma unroll
    for (int k = 0; k < 6; k++) {
        s += v[k].x + v[k].y + v[k].z + v[k].w;
        q += v[k].x * v[k].x + v[k].y * v[k].y + v[k].z * v[k].z + v[k].w * v[k].w;
    }
#pragma unroll
    for (int off = 16; off; off >>= 1) {
        s += __shfl_xor_sync(0xffffffffu, s, off);
        q += __shfl_xor_sync(0xffffffffu, q, off);
    }
    float mean = s * (1.f / 768.f);
    float inv  = rsqrtf(q * (1.f / 768.f) - mean * mean + 1e-5f);
#pragma unroll
    for (int k = 0; k < 6; k++) {
        int d = (k * 32 + lane) * 4;
        float4 gv = *(const float4*)(g + d);
        float4 bv = *(const float4*)(bb + d);
        float y0 = (v[k].x - mean) * inv * gv.x + bv.x;
        float y1 = (v[k].y - mean) * inv * gv.y + bv.y;
        float y2 = (v[k].z - mean) * inv * gv.z + bv.z;
        float y3 = (v[k].w - mean) * inv * gv.w + bv.w;
        if (EXPOUT) {
            uint2 o;
            o.x = packh2(y0, y1);
            o.y = packh2(y2, y3);
            *(uint2*)((__half*)outp + (size_t)row * Dm + d) = o;
        } else {
            *(float4*)((float*)outp + (size_t)row * out_stride + d) =
                make_float4(y0, y1, y2, y3);
        }
    }
}

// ======== fp16 HMMA GEMM (proven config): C[M,N] = A[M,Kp] @ W[N,Kp]^T ========
// BM=128, BN=128, warp 64x32, 256 thr, 2 CTA/SM, 3-stage cp.async, K-tile 32.
// MODE 0: +bias fp32; 1: +bias fp16; 2: +bias+res fp32; 3: quick_gelu(+bias) fp16
#define BKt 32
#define SKS 40
#define STG (128*SKS)
#define GSM (6*STG*2)    // 61440 bytes

template <int MODE>
__global__ __launch_bounds__(256, 2)
void bgemm_kernel(const __half* __restrict__ A, const __half* __restrict__ W,
                  const float* __restrict__ bias, const float* __restrict__ res,
                  void* __restrict__ Cout, int Kp, int N, int Mreal, int resStride) {
    extern __shared__ __half smem[];
    __half* sAb = smem;
    __half* sBb = smem + 3 * STG;

    int tid = threadIdx.x, lane = tid & 31, warp = tid >> 5;
    int m0 = blockIdx.y * 128, n0 = blockIdx.x * 128;
    int wm = (warp >> 2) * 64, wn = (warp & 3) * 32;
    int lrow = tid >> 2, lko = (tid & 3) << 3;

    const __half* Ag0 = A + (size_t)(m0 + lrow) * Kp + lko;
    const __half* Ag1 = A + (size_t)(m0 + lrow + 64) * Kp + lko;
    const __half* Bg0 = W + (size_t)(n0 + lrow) * Kp + lko;
    const __half* Bg1 = W + (size_t)(n0 + lrow + 64) * Kp + lko;

    float acc[4][4][4];
#pragma unroll
    for (int i = 0; i < 4; i++)
#pragma unroll
        for (int j = 0; j < 4; j++)
#pragma unroll
            for (int e = 0; e < 4; e++) acc[i][j][e] = 0.f;

    auto load_stage = [&](int st, int k0) {
        __half* a = sAb + st * STG + lrow * SKS + lko;
        __half* b = sBb + st * STG + lrow * SKS + lko;
        cp16(a,            Ag0 + k0);
        cp16(a + 64 * SKS, Ag1 + k0);
        cp16(b,            Bg0 + k0);
        cp16(b + 64 * SKS, Bg1 + k0);
        asm volatile("cp.async.commit_group;\n" ::: "memory");
    };

    int nk = Kp / BKt;
    load_stage(0, 0);
    load_stage(1, BKt);

    int cs = 0, ls = 2;
    for (int t = 0; t < nk; t++) {
        if (t + 1 < nk) asm volatile("cp.async.wait_group 1;\n" ::: "memory");
        else            asm volatile("cp.async.wait_group 0;\n" ::: "memory");
        __syncthreads();
        if (t + 2 < nk) load_stage(ls, (t + 2) * BKt);
        ls = (ls == 2) ? 0 : ls + 1;

        const __half* as = sAb + cs * STG;
        const __half* bs = sBb + cs * STG;
        cs = (cs == 2) ? 0 : cs + 1;
#pragma unroll
        for (int kk = 0; kk < 2; kk++) {
            int kof = kk * 16 + ((lane >> 4) << 3);
            int rrow = lane & 15;
            unsigned ar[4][4];
#pragma unroll
            for (int mi = 0; mi < 4; mi++)
                ldm4(ar[mi], &as[(wm + mi * 16 + rrow) * SKS + kof]);
            unsigned br[2][4];
#pragma unroll
            for (int p = 0; p < 2; p++)
                ldm4(br[p], &bs[(wn + p * 16 + rrow) * SKS + kof]);
#pragma unroll
            for (int mi = 0; mi < 4; mi++)
#pragma unroll
                for (int nj = 0; nj < 4; nj++)
                    mma16816(acc[mi][nj], ar[mi], br[nj >> 1][nj & 1], br[nj >> 1][(nj & 1) + 2]);
        }
    }

    int group = lane >> 2, tig = lane & 3;
#pragma unroll
    for (int mi = 0; mi < 4; mi++) {
#pragma unroll
        for (int nj = 0; nj < 4; nj++) {
            int col = n0 + wn + nj * 8 + tig * 2;
            float bx = 0.f, by = 0.f;
            if (bias) { bx = bias[col]; by = bias[col + 1]; }
#pragma unroll
            for (int h = 0; h < 2; h++) {
                int row = m0 + wm + mi * 16 + group + h * 8;
                if (row >= Mreal) continue;
                float c0 = acc[mi][nj][h * 2 + 0] + bx;
                float c1 = acc[mi][nj][h * 2 + 1] + by;
                if (MODE == 2) {
                    float2 rr = *(const float2*)(res + (size_t)row * resStride + col);
                    c0 += rr.x; c1 += rr.y;
                }
                if (MODE == 3) {
                    __half2 hp;
                    hp.x = __float2half(qgelu(c0));
                    hp.y = __float2half(qgelu(c1));
                    *(__half2*)((__half*)Cout + (size_t)row * N + col) = hp;
                } else if (MODE == 1) {
                    __half2 hp;
                    hp.x = __float2half(c0);
                    hp.y = __float2half(c1);
                    *(__half2*)((__half*)Cout + (size_t)row * N + col) = hp;
                } else {
                    *(float2*)((float*)Cout + (size_t)row * N + col) = make_float2(c0, c1);
                }
            }
        }
    }
}

// ======== wide-tile fp16 GEMM for long-K (fc2): BM=128, BN=256, warp 64x64, 1 CTA/SM ====
// MODE 2 epilogue only: +bias +res, fp32 out.
#define ASTW (128*SKS)
#define BSTW (256*SKS)
#define GSMW (3*(ASTW+BSTW)*2)   // 92160 bytes

__global__ __launch_bounds__(256, 1)
void bgemm_wide_kernel(const __half* __restrict__ A, const __half* __restrict__ W,
                       const float* __restrict__ bias, const float* __restrict__ res,
                       float* __restrict__ Cout, int Kp, int N, int Mreal, int resStride) {
    extern __shared__ __half smem[];
    __half* sAb = smem;                  // 3 * ASTW
    __half* sBb = smem + 3 * ASTW;       // 3 * BSTW

    int tid = threadIdx.x, lane = tid & 31, warp = tid >> 5;
    int m0 = blockIdx.y * 128, n0 = blockIdx.x * 256;
    int wm = (warp >> 2) * 64, wn = (warp & 3) * 64;
    int lrow = tid >> 2, lko = (tid & 3) << 3;

    float acc[4][8][4];
#pragma unroll
    for (int i = 0; i < 4; i++)
#pragma unroll
        for (int j = 0; j < 8; j++)
#pragma unroll
            for (int e = 0; e < 4; e++) acc[i][j][e] = 0.f;

    auto load_stage = [&](int st, int k0) {
        __half* a = sAb + st * ASTW;
        __half* b = sBb + st * BSTW;
        cp16(a + lrow * SKS + lko,        A + (size_t)(m0 + lrow) * Kp + k0 + lko);
        cp16(a + (lrow + 64) * SKS + lko, A + (size_t)(m0 + lrow + 64) * Kp + k0 + lko);
#pragma unroll
        for (int jb = 0; jb < 4; jb++)
            cp16(b + (lrow + jb * 64) * SKS + lko,
                 W + (size_t)(n0 + lrow + jb * 64) * Kp + k0 + lko);
        asm volatile("cp.async.commit_group;\n" ::: "memory");
    };

    int nk = Kp / BKt;
    load_stage(0, 0);
    load_stage(1, BKt);

    int cs = 0, ls = 2;
    for (int t = 0; t < nk; t++) {
        if (t + 1 < nk) asm volatile("cp.async.wait_group 1;\n" ::: "memory");
        else            asm volatile("cp.async.wait_group 0;\n" ::: "memory");
        __syncthreads();
        if (t + 2 < nk) load_stage(ls, (t + 2) * BKt);
        ls = (ls == 2) ? 0 : ls + 1;

        const __half* as = sAb + cs * ASTW;
        const __half* bs = sBb + cs * BSTW;
        cs = (cs == 2) ? 0 : cs + 1;
#pragma unroll
        for (int kk = 0; kk < 2; kk++) {
            int kof = kk * 16 + ((lane >> 4) << 3);
            int rrow = lane & 15;
            unsigned ar[4][4];
#pragma unroll
            for (int mi = 0; mi < 4; mi++)
                ldm4(ar[mi], &as[(wm + mi * 16 + rrow) * SKS + kof]);
            unsigned br[4][4];
#pragma unroll
            for (int p = 0; p < 4; p++)
                ldm4(br[p], &bs[(wn + p * 16 + rrow) * SKS + kof]);
#pragma unroll
            for (int mi = 0; mi < 4; mi++)
#pragma unroll
                for (int nj = 0; nj < 8; nj++)
                    mma16816(acc[mi][nj], ar[mi],
                             br[nj >> 1][nj & 1], br[nj >> 1][(nj & 1) + 2]);
        }
    }

    int group = lane >> 2, tig = lane & 3;
#pragma unroll
    for (int mi = 0; mi < 4; mi++) {
#pragma unroll
        for (int nj = 0; nj < 8; nj++) {
            int col = n0 + wn + nj * 8 + tig * 2;
            float bx = bias[col], by = bias[col + 1];
#pragma unroll
            for (int h = 0; h < 2; h++) {
                int row = m0 + wm + mi * 16 + group + h * 8;
                if (row >= Mreal) continue;
                float2 rr = *(const float2*)(res + (size_t)row * resStride + col);
                float c0 = acc[mi][nj][h * 2 + 0] + bx + rr.x;
                float c1 = acc[mi][nj][h * 2 + 1] + by + rr.y;
                *(float2*)(Cout + (size_t)row * N + col) = make_float2(c0, c1);
            }
        }
    }
}

// ======== tensor-core attention: fp16 qkv input; mma QK + PV ========
#define QS 72
#define VTS 216
#define NT 208
#define ATTN_SMEM_BYTES ((NT*QS + NT*QS + 64*VTS)*2)   // 87552
__global__ __launch_bounds__(256, 1)
void attn_kernel(const __half* __restrict__ qkv, __half* __restrict__ o) {
    extern __shared__ __half ash[];
    __half* sQ  = ash;
    __half* sK  = sQ + NT * QS;
    __half* sVT = sK + NT * QS;
    int bh = blockIdx.x;
    int b = bh / Hn, hh = bh % Hn;
    int tid = threadIdx.x;
    size_t base = (size_t)b * STOK * NQKV + (size_t)hh * DHd;

    for (int idx = tid; idx < 3 * 32; idx += 256) {
        int r = 205 + idx / 32, d2 = idx % 32;
        *(__half2*)(sQ + r * QS + 2 * d2) = __floats2half2_rn(0.f, 0.f);
        *(__half2*)(sK + r * QS + 2 * d2) = __floats2half2_rn(0.f, 0.f);
    }
    for (int idx = tid; idx < 64 * 3; idx += 256) {
        int d = idx / 3, t = 205 + idx % 3;
        sVT[d * VTS + t] = __float2half(0.f);
    }
    for (int idx = tid; idx < STOK * 32; idx += 256) {
        int j = idx >> 5, d2 = idx & 31;
        const __half2* rp = (const __half2*)(qkv + base + (size_t)j * NQKV) + d2;
        __half2 qq = rp[0];
        __half2 kk = rp[384];
        __half2 vv = rp[768];
        *(__half2*)(sQ + j * QS + 2 * d2) = qq;
        *(__half2*)(sK + j * QS + 2 * d2) = kk;
        sVT[(2 * d2) * VTS + j]     = __low2half(vv);
        sVT[(2 * d2 + 1) * VTS + j] = __high2half(vv);
    }
    __syncthreads();

    int warp = tid >> 5, lane = tid & 31;
    int group = lane >> 2, tig = lane & 3;
    int rrow = lane & 15, khalf = (lane >> 4) << 3;

    for (int qt = warp; qt < 13; qt += 8) {
        float S[26][4];
#pragma unroll
        for (int f = 0; f < 26; f++)
#pragma unroll
            for (int e = 0; e < 4; e++) S[f][e] = 0.f;

#pragma unroll
        for (int kt = 0; kt < 4; kt++) {
            unsigned aq[4];
            ldm4(aq, sQ + (qt * 16 + rrow) * QS + kt * 16 + khalf);
#pragma unroll
            for (int nt = 0; nt < 13; nt++) {
                unsigned kb[4];
                ldm4(kb, sK + (nt * 16 + rrow) * QS + kt * 16 + khalf);
                mma16816(S[2 * nt],     aq, kb[0], kb[2]);
                mma16816(S[2 * nt + 1], aq, kb[1], kb[3]);
            }
        }

        float mx0 = -1e30f, mx1 = -1e30f;
#pragma unroll
        for (int f = 0; f < 26; f++) {
            int c0 = f * 8 + 2 * tig;
            if (c0 < STOK)     { mx0 = fmaxf(mx0, S[f][0]); mx1 = fmaxf(mx1, S[f][2]); }
            if (c0 + 1 < STOK) { mx0 = fmaxf(mx0, S[f][1]); mx1 = fmaxf(mx1, S[f][3]); }
        }
        mx0 = fmaxf(mx0, __shfl_xor_sync(0xffffffffu, mx0, 1));
        mx0 = fmaxf(mx0, __shfl_xor_sync(0xffffffffu, mx0, 2));
        mx1 = fmaxf(mx1, __shfl_xor_sync(0xffffffffu, mx1, 1));
        mx1 = fmaxf(mx1, __shfl_xor_sync(0xffffffffu, mx1, 2));

        float sum0 = 0.f, sum1 = 0.f;
        unsigned Pg[26], Pg8[26];
#pragma unroll
        for (int f = 0; f < 26; f++) {
            int c0 = f * 8 + 2 * tig;
            float e0 = (c0 < STOK)     ? __expf(S[f][0] - mx0) : 0.f;
            float e1 = (c0 + 1 < STOK) ? __expf(S[f][1] - mx0) : 0.f;
            float e2 = (c0 < STOK)     ? __expf(S[f][2] - mx1) : 0.f;
            float e3 = (c0 + 1 < STOK) ? __expf(S[f][3] - mx1) : 0.f;
            sum0 += e0 + e1;
            sum1 += e2 + e3;
            Pg[f]  = packh2(e0, e1);
            Pg8[f] = packh2(e2, e3);
        }
        sum0 += __shfl_xor_sync(0xffffffffu, sum0, 1);
        sum0 += __shfl_xor_sync(0xffffffffu, sum0, 2);
        sum1 += __shfl_xor_sync(0xffffffffu, sum1, 1);
        sum1 += __shfl_xor_sync(0xffffffffu, sum1, 2);
        float inv0 = 1.f / sum0, inv1 = 1.f / sum1;

        float O[8][4];
#pragma unroll
        for (int f = 0; f < 8; f++)
#pragma unroll
            for (int e = 0; e < 4; e++) O[f][e] = 0.f;

#pragma unroll
        for (int kt = 0; kt < 13; kt++) {
            unsigned ap[4] = {Pg[2 * kt], Pg8[2 * kt], Pg[2 * kt + 1], Pg8[2 * kt + 1]};
#pragma unroll
            for (int vd = 0; vd < 4; vd++) {
                unsigned vb[4];
                ldm4(vb, sVT + (vd * 16 + rrow) * VTS + kt * 16 + khalf);
                mma16816(O[2 * vd],     ap, vb[0], vb[2]);
                mma16816(O[2 * vd + 1], ap, vb[1], vb[3]);
            }
        }

        int q0 = qt * 16 + group;
        int q1 = q0 + 8;
#pragma unroll
        for (int nt = 0; nt < 8; nt++) {
            int col = hh * DHd + nt * 8 + 2 * tig;
            if (q0 < STOK) {
                __half2 hp = __floats2half2_rn(O[nt][0] * inv0, O[nt][1] * inv0);
                *(__half2*)(o + (size_t)(b * STOK + q0) * Dm + col) = hp;
            }
            if (q1 < STOK) {
                __half2 hp = __floats2half2_rn(O[nt][2] * inv1, O[nt][3] * inv1);
                *(__half2*)(o + (size_t)(b * STOK + q1) * Dm + col) = hp;
            }
        }
    }
}

// ---------------- host orchestration ----------------
extern "C" void kernel_launch(void* const* d_in, const int* in_sizes, int n_in,
                              void* d_out, int out_size) {
    const float* image   = (const float*)d_in[0];
    const float* gprompt = (const float*)d_in[1];
    const float* patch_w = (const float*)d_in[2];
    const float* cls_emb = (const float*)d_in[3];
    const float* pos_emb = (const float*)d_in[4];
    const float* pre_g   = (const float*)d_in[5];
    const float* pre_b   = (const float*)d_in[6];
    const float* ln1_g   = (const float*)d_in[7];
    const float* ln1_b   = (const float*)d_in[8];
    const float* qw      = (const float*)d_in[9];
    const float* qb      = (const float*)d_in[10];
    const float* kw      = (const float*)d_in[11];
    const float* kb      = (const float*)d_in[12];
    const float* vw      = (const float*)d_in[13];
    const float* vb      = (const float*)d_in[14];
    const float* ow      = (const float*)d_in[15];
    const float* ob      = (const float*)d_in[16];
    const float* ln2_g   = (const float*)d_in[17];
    const float* ln2_b   = (const float*)d_in[18];
    const float* fc1_w   = (const float*)d_in[19];
    const float* fc1_b   = (const float*)d_in[20];
    const float* fc2_w   = (const float*)d_in[21];
    const float* fc2_b   = (const float*)d_in[22];
    const float* post_g  = (const float*)d_in[23];
    const float* post_b  = (const float*)d_in[24];
    float* out = (float*)d_out;

    float *x, *feat, *bqkv;
    __half *qkvh, *ae1, *ae2, *wqkvd, *wod, *w1d, *w2d, *wpd;
    cudaGetSymbolAddress((void**)&x,    g_x);
    cudaGetSymbolAddress((void**)&feat, g_feat);
    cudaGetSymbolAddress((void**)&qkvh, g_qkvh);
    cudaGetSymbolAddress((void**)&bqkv, g_bqkv);
    cudaGetSymbolAddress((void**)&ae1,  g_ae1);
    cudaGetSymbolAddress((void**)&ae2,  g_ae2);
    cudaGetSymbolAddress((void**)&wqkvd, g_wqkv);
    cudaGetSymbolAddress((void**)&wod,  g_wo);
    cudaGetSymbolAddress((void**)&w1d,  g_w1);
    cudaGetSymbolAddress((void**)&w2d,  g_w2);
    cudaGetSymbolAddress((void**)&wpd,  g_wp);

    cudaFuncSetAttribute(attn_kernel, cudaFuncAttributeMaxDynamicSharedMemorySize, ATTN_SMEM_BYTES);
    cudaFuncSetAttribute(bgemm_kernel<0>, cudaFuncAttributeMaxDynamicSharedMemorySize, GSM);
    cudaFuncSetAttribute(bgemm_kernel<1>, cudaFuncAttributeMaxDynamicSharedMemorySize, GSM);
    cudaFuncSetAttribute(bgemm_kernel<2>, cudaFuncAttributeMaxDynamicSharedMemorySize, GSM);
    cudaFuncSetAttribute(bgemm_kernel<3>, cudaFuncAttributeMaxDynamicSharedMemorySize, GSM);
    cudaFuncSetAttribute(bgemm_wide_kernel, cudaFuncAttributeMaxDynamicSharedMemorySize, GSMW);

    // --- preamble; position #4 (1-based) = conv GEMM for ncu capture ---
    {
        long long n;
        n = (long long)Dm * Dm / 4;                                        // 1
        wconv_kernel<<<(unsigned)((n + 255) / 256), 256>>>(patch_w, wpd, n);
        im2col_kernel<<<(MPATCH * Dm / 2 + 255) / 256, 256>>>(image, ae1);  // 2
        bconv_qkv_kernel<<<(Lnum * NQKV + 255) / 256, 256>>>(qb, kb, vb, bqkv); // 3
        // 4: conv GEMM  <- ncu capture target
        bgemm_kernel<0><<<dim3(Dm / 128, MPATCH / 128), 256, GSM>>>(
            ae1, wpd, nullptr, nullptr, feat, Dm, Dm, MPATCH, 0);
        n = (long long)Lnum * NQKV * (Dm / 4);                              // 5
        wconv_qkv_kernel<<<(unsigned)((n + 255) / 256), 256>>>(qw, kw, vw, wqkvd);
        assemble_kernel<<<(MTOK * Dm / 4 + 255) / 256, 256>>>(feat, cls_emb, pos_emb, gprompt, x); // 6
        ln_kernel<0><<<(MTOK + 7) / 8, 256>>>(x, pre_g, pre_b, x, Dm, Dm, nullptr, 0, MTOK); // 7
        n = (long long)Lnum * Dm * Dm / 4;                                  // 8
        wconv_kernel<<<(unsigned)((n + 255) / 256), 256>>>(ow, wod, n);
        n = (long long)Lnum * FFd * Dm / 4;                                 // 9
        wconv_kernel<<<(unsigned)((n + 255) / 256), 256>>>(fc1_w, w1d, n);
        n = (long long)Lnum * Dm * FFd / 4;                                 // 10
        wconv_kernel<<<(unsigned)((n + 255) / 256), 256>>>(fc2_w, w2d, n);
    }

    dim3 g768(Dm / 128, MPAD / 128);    // (6, 103)
    dim3 gqkv(NQKV / 128, MPAD / 128);  // (18, 103)
    dim3 gff(FFd / 128, MPAD / 128);    // (24, 103)
    dim3 gfc2w(Dm / 256, MPAD / 128);   // (3, 103) wide tiles
    int lnGrid = (MTOK + 7) / 8;

    for (int l = 0; l < Lnum; l++) {
        // attention (ln1 folds the prompt replacement for l>0)
        ln_kernel<1><<<lnGrid, 256>>>(x, ln1_g + (size_t)l * Dm, ln1_b + (size_t)l * Dm,
                                      ae1, Dm, 0, gprompt, l, MTOK);
        bgemm_kernel<1><<<gqkv, 256, GSM>>>(
            ae1, wqkvd + (size_t)l * NQKV * Dm, bqkv + (size_t)l * NQKV,
            nullptr, qkvh, Dm, NQKV, MTOK, 0);
        attn_kernel<<<Bsz * Hn, 256, ATTN_SMEM_BYTES>>>(qkvh, ae1);
        bgemm_kernel<2><<<g768, 256, GSM>>>(
            ae1, wod + (size_t)l * Dm * Dm, ob + (size_t)l * Dm,
            x, x, Dm, Dm, MTOK, Dm);
        // MLP
        ln_kernel<1><<<lnGrid, 256>>>(x, ln2_g + (size_t)l * Dm, ln2_b + (size_t)l * Dm,
                                      ae1, Dm, 0, nullptr, 0, MTOK);
        bgemm_kernel<3><<<gff, 256, GSM>>>(
            ae1, w1d + (size_t)l * FFd * Dm, fc1_b + (size_t)l * FFd,
            nullptr, ae2, Dm, FFd, MTOK, 0);
        bgemm_wide_kernel<<<gfc2w, 256, GSMW>>>(
            ae2, w2d + (size_t)l * Dm * FFd, fc2_b + (size_t)l * Dm,
            x, x, FFd, Dm, MTOK, Dm);
    }

    ln_kernel<0><<<(Bsz + 7) / 8, 256>>>(x, post_g, post_b, out, STOK * Dm, Dm,
                                         nullptr, 0, Bsz);
}

// round 15
// speedup vs baseline: 1.0345x; 1.0345x over previous
#include <cuda_runtime.h>
#include <cuda_fp16.h>
#include <math.h>
#include <stdint.h>

// ---------------- problem constants ----------------
#define Bsz    64
#define Dm     768
#define Hn     12
#define DHd    64
#define Lnum   12
#define FFd    3072
#define NPRn   8
#define STOK   205
#define NPATCH 196
#define MTOK   (Bsz*STOK)     // 13120
#define MPATCH (Bsz*NPATCH)   // 12544 = 98*128
#define MPAD   13184          // 103*128 >= MTOK
#define NQKV   2304           // fused q|k|v output width

// ---------------- static device scratch ----------------
__device__ float  g_x[MPAD*Dm];
__device__ float  g_feat[MPATCH*Dm];              // conv output fp32
__device__ __half g_qkvh[(size_t)MPAD*NQKV];      // packed q|k|v fp16
__device__ float  g_bqkv[(size_t)Lnum*NQKV];
__device__ __half g_ae1[(size_t)MPAD*Dm];         // fp16 activations (K=768 GEMMs)
__device__ __half g_ae2[(size_t)MPAD*FFd];        // fp16 MLP hidden
__device__ __half g_wqkv[(size_t)Lnum*NQKV*Dm];
__device__ __half g_wo[(size_t)Lnum*Dm*Dm];
__device__ __half g_w1[(size_t)Lnum*FFd*Dm];
__device__ __half g_w2[(size_t)Lnum*Dm*FFd];
__device__ __half g_wp[(size_t)Dm*Dm];

// ---------------- helpers ----------------
__device__ __forceinline__ float qgelu(float x) {
    return x / (1.f + expf(-1.702f * x));
}
__device__ __forceinline__ void cp16(void* s, const void* g) {
    unsigned sa = (unsigned)__cvta_generic_to_shared(s);
    asm volatile("cp.async.ca.shared.global [%0], [%1], 16;\n" :: "r"(sa), "l"(g));
}
__device__ __forceinline__ void ldm4(unsigned* r, const __half* p) {
    unsigned s = (unsigned)__cvta_generic_to_shared(p);
    asm volatile("ldmatrix.sync.aligned.m8n8.x4.shared.b16 {%0,%1,%2,%3}, [%4];"
                 : "=r"(r[0]), "=r"(r[1]), "=r"(r[2]), "=r"(r[3]) : "r"(s));
}
__device__ __forceinline__ void mma16816(float* d, const unsigned* a, unsigned b0, unsigned b1) {
    asm volatile("mma.sync.aligned.m16n8k16.row.col.f32.f16.f16.f32 "
                 "{%0,%1,%2,%3}, {%4,%5,%6,%7}, {%8,%9}, {%0,%1,%2,%3};"
                 : "+f"(d[0]), "+f"(d[1]), "+f"(d[2]), "+f"(d[3])
                 : "r"(a[0]), "r"(a[1]), "r"(a[2]), "r"(a[3]), "r"(b0), "r"(b1));
}
__device__ __forceinline__ unsigned packh2(float a, float b) {
    __half2 h = __floats2half2_rn(a, b);
    return *(unsigned*)&h;
}

// ---------------- weight conversion: fp32 -> fp16 (vectorized x4) ----------------
__global__ __launch_bounds__(256) void wconv_kernel(const float* __restrict__ src,
                                                    __half* __restrict__ dst,
                                                    long long total4) {
    long long idx = (long long)blockIdx.x * 256 + threadIdx.x;
    if (idx >= total4) return;
    float4 v = ((const float4*)src)[idx];
    uint2 o;
    o.x = packh2(v.x, v.y);
    o.y = packh2(v.z, v.w);
    ((uint2*)dst)[idx] = o;
}

// ---------------- fused QKV weight conversion (scale folded into q rows, x4) -----------
__global__ __launch_bounds__(256) void wconv_qkv_kernel(const float* __restrict__ qw,
                                                        const float* __restrict__ kw,
                                                        const float* __restrict__ vw,
                                                        __half* __restrict__ dst) {
    long long idx = (long long)blockIdx.x * 256 + threadIdx.x;   // in float4 units
    if (idx >= (long long)Lnum * NQKV * (Dm / 4)) return;
    int k4 = (int)(idx % (Dm / 4));
    long long rowall = idx / (Dm / 4);
    int rr = (int)(rowall % NQKV);
    int l  = (int)(rowall / NQKV);
    float4 v;
    float sc = 1.f;
    if (rr < 768) {
        v = *(const float4*)(qw + (((size_t)l * Dm + rr) * Dm) + 4 * k4);
        sc = 0.125f;
    } else if (rr < 1536) {
        v = *(const float4*)(kw + (((size_t)l * Dm + (rr - 768)) * Dm) + 4 * k4);
    } else {
        v = *(const float4*)(vw + (((size_t)l * Dm + (rr - 1536)) * Dm) + 4 * k4);
    }
    uint2 o;
    o.x = packh2(v.x * sc, v.y * sc);
    o.y = packh2(v.z * sc, v.w * sc);
    ((uint2*)dst)[idx] = o;
}

__global__ __launch_bounds__(256) void bconv_qkv_kernel(const float* __restrict__ qb,
                                                        const float* __restrict__ kb,
                                                        const float* __restrict__ vb,
                                                        float* __restrict__ out) {
    int idx = blockIdx.x * 256 + threadIdx.x;
    if (idx >= Lnum * NQKV) return;
    int rr = idx % NQKV, l = idx / NQKV;
    float v;
    if (rr < 768)       v = qb[l * Dm + rr] * 0.125f;
    else if (rr < 1536) v = kb[l * Dm + (rr - 768)];
    else                v = vb[l * Dm + (rr - 1536)];
    out[idx] = v;
}

// ---------------- im2col fp16 (x2): image -> ae1 [MPATCH, 768] ----------------
__global__ __launch_bounds__(256) void im2col_kernel(const float* __restrict__ img,
                                                     __half* __restrict__ out) {
    int idx = blockIdx.x * 256 + threadIdx.x;     // in pairs
    if (idx >= MPATCH * Dm / 2) return;
    int k = (idx % (Dm / 2)) * 2;
    int m = idx / (Dm / 2);
    int b = m / NPATCH, p = m % NPATCH;
    int py = p / 14, px = p % 14;
    int c = k >> 8, i = (k >> 4) & 15, j = k & 15;
    float2 v = *(const float2*)(img + (((size_t)b * 3 + c) * 224 + (py * 16 + i)) * 224
                                + (px * 16 + j));
    ((unsigned*)out)[idx] = packh2(v.x, v.y);
}

// ---------------- assemble (x4) ----------------
__global__ __launch_bounds__(256) void assemble_kernel(const float* __restrict__ feat,
                                                       const float* __restrict__ cls,
                                                       const float* __restrict__ pos,
                                                       const float* __restrict__ gp,
                                                       float* __restrict__ x) {
    int idx = blockIdx.x * blockDim.x + threadIdx.x;   // in float4 units
    if (idx >= MTOK * Dm / 4) return;
    int d = (idx % (Dm / 4)) * 4;
    int s = (idx / (Dm / 4)) % STOK;
    int b = idx / ((Dm / 4) * STOK);
    float4 v;
    if (s == 0) {
        float4 cv = *(const float4*)(cls + d);
        float4 pv = *(const float4*)(pos + d);
        v = make_float4(cv.x + pv.x, cv.y + pv.y, cv.z + pv.z, cv.w + pv.w);
    } else if (s < 197) {
        float4 fv = *(const float4*)(feat + ((size_t)(b * NPATCH + s - 1)) * Dm + d);
        float4 pv = *(const float4*)(pos + (size_t)s * Dm + d);
        v = make_float4(fv.x + pv.x, fv.y + pv.y, fv.z + pv.z, fv.w + pv.w);
    } else {
        v = *(const float4*)(gp + (((size_t)b * Lnum + 0) * NPRn + (s - 197)) * Dm + d);
    }
    ((float4*)x)[idx] = v;
}

// ---------------- LayerNorm (R13-proven block version, fused prompt replacement) --------
// EXPOUT=0: fp32 out (out_stride). EXPOUT=1: fp16 out (stride 768).
// If gp != nullptr && layer>0: rows with s>=197 read the layer's prompt instead of x,
// AND write that raw prompt back into x (residual stream).
template <int EXPOUT>
__global__ __launch_bounds__(256) void ln_kernel(float* __restrict__ x,
                                                 const float* __restrict__ g,
                                                 const float* __restrict__ bb,
                                                 void* __restrict__ outp,
                                                 int in_stride, int out_stride,
                                                 const float* __restrict__ gp, int layer) {
    int row = blockIdx.x;
    const float* src = x + (size_t)row * in_stride;
    bool isPrompt = false;
    if (EXPOUT && gp != nullptr && layer > 0) {
        int s = row % STOK;
        if (s >= 197) {
            int b = row / STOK;
            src = gp + (((size_t)b * Lnum + layer) * NPRn + (s - 197)) * Dm;
            isPrompt = true;
        }
    }
    int t = threadIdx.x;
    float v0 = src[t], v1 = src[t + 256], v2 = src[t + 512];
    if (isPrompt) {
        float* xr = x + (size_t)row * in_stride;
        xr[t] = v0; xr[t + 256] = v1; xr[t + 512] = v2;
    }
    float s = v0 + v1 + v2;
    float q = v0 * v0 + v1 * v1 + v2 * v2;
#pragma unroll
    for (int off = 16; off; off >>= 1) {
        s += __shfl_xor_sync(0xffffffffu, s, off);
        q += __shfl_xor_sync(0xffffffffu, q, off);
    }
    __shared__ float ws[8], wq[8], stat[2];
    int w = t >> 5, lane = t & 31;
    if (lane == 0) { ws[w] = s; wq[w] = q; }
    __syncthreads();
    if (t < 32) {
        float s2 = (t < 8) ? ws[t] : 0.f;
        float q2 = (t < 8) ? wq[t] : 0.f;
#pragma unroll
        for (int off = 4; off; off >>= 1) {
            s2 += __shfl_xor_sync(0xffffffffu, s2, off);
            q2 += __shfl_xor_sync(0xffffffffu, q2, off);
        }
        if (t == 0) {
            float mean = s2 * (1.f / 768.f);
            float var  = q2 * (1.f / 768.f) - mean * mean;
            stat[0] = mean;
            stat[1] = rsqrtf(var + 1e-5f);
        }
    }
    __syncthreads();
    float mean = stat[0], inv = stat[1];
    float y0 = (v0 - mean) * inv * g[t]       + bb[t];
    float y1 = (v1 - mean) * inv * g[t + 256] + bb[t + 256];
    float y2 = (v2 - mean) * inv * g[t + 512] + bb[t + 512];
    if (EXPOUT) {
        __half* o = (__half*)outp + (size_t)row * Dm;
        o[t]       = __float2half(y0);
        o[t + 256] = __float2half(y1);
        o[t + 512] = __float2half(y2);
    } else {
        float* o = (float*)outp + (size_t)row * out_stride;
        o[t] = y0; o[t + 256] = y1; o[t + 512] = y2;
    }
}

// ======== fp16 HMMA GEMM (proven config): C[M,N] = A[M,Kp] @ W[N,Kp]^T ========
// BM=128, BN=128, warp 64x32, 256 thr, 2 CTA/SM, 3-stage cp.async, K-tile 32.
// MODE 0: +bias fp32; 1: +bias fp16; 2: +bias+res fp32; 3: quick_gelu(+bias) fp16
#define BKt 32
#define SKS 40
#define STG (128*SKS)
#define GSM (6*STG*2)    // 61440 bytes

template <int MODE>
__global__ __launch_bounds__(256, 2)
void bgemm_kernel(const __half* __restrict__ A, const __half* __restrict__ W,
                  const float* __restrict__ bias, const float* __restrict__ res,
                  void* __restrict__ Cout, int Kp, int N, int Mreal, int resStride) {
    extern __shared__ __half smem[];
    __half* sAb = smem;
    __half* sBb = smem + 3 * STG;

    int tid = threadIdx.x, lane = tid & 31, warp = tid >> 5;
    int m0 = blockIdx.y * 128, n0 = blockIdx.x * 128;
    int wm = (warp >> 2) * 64, wn = (warp & 3) * 32;
    int lrow = tid >> 2, lko = (tid & 3) << 3;

    const __half* Ag0 = A + (size_t)(m0 + lrow) * Kp + lko;
    const __half* Ag1 = A + (size_t)(m0 + lrow + 64) * Kp + lko;
    const __half* Bg0 = W + (size_t)(n0 + lrow) * Kp + lko;
    const __half* Bg1 = W + (size_t)(n0 + lrow + 64) * Kp + lko;

    float acc[4][4][4];
#pragma unroll
    for (int i = 0; i < 4; i++)
#pragma unroll
        for (int j = 0; j < 4; j++)
#pragma unroll
            for (int e = 0; e < 4; e++) acc[i][j][e] = 0.f;

    auto load_stage = [&](int st, int k0) {
        __half* a = sAb + st * STG + lrow * SKS + lko;
        __half* b = sBb + st * STG + lrow * SKS + lko;
        cp16(a,            Ag0 + k0);
        cp16(a + 64 * SKS, Ag1 + k0);
        cp16(b,            Bg0 + k0);
        cp16(b + 64 * SKS, Bg1 + k0);
        asm volatile("cp.async.commit_group;\n" ::: "memory");
    };

    int nk = Kp / BKt;
    load_stage(0, 0);
    load_stage(1, BKt);

    int cs = 0, ls = 2;
    for (int t = 0; t < nk; t++) {
        if (t + 1 < nk) asm volatile("cp.async.wait_group 1;\n" ::: "memory");
        else            asm volatile("cp.async.wait_group 0;\n" ::: "memory");
        __syncthreads();
        if (t + 2 < nk) load_stage(ls, (t + 2) * BKt);
        ls = (ls == 2) ? 0 : ls + 1;

        const __half* as = sAb + cs * STG;
        const __half* bs = sBb + cs * STG;
        cs = (cs == 2) ? 0 : cs + 1;
#pragma unroll
        for (int kk = 0; kk < 2; kk++) {
            int kof = kk * 16 + ((lane >> 4) << 3);
            int rrow = lane & 15;
            unsigned ar[4][4];
#pragma unroll
            for (int mi = 0; mi < 4; mi++)
                ldm4(ar[mi], &as[(wm + mi * 16 + rrow) * SKS + kof]);
            unsigned br[2][4];
#pragma unroll
            for (int p = 0; p < 2; p++)
                ldm4(br[p], &bs[(wn + p * 16 + rrow) * SKS + kof]);
#pragma unroll
            for (int mi = 0; mi < 4; mi++)
#pragma unroll
                for (int nj = 0; nj < 4; nj++)
                    mma16816(acc[mi][nj], ar[mi], br[nj >> 1][nj & 1], br[nj >> 1][(nj & 1) + 2]);
        }
    }

    int group = lane >> 2, tig = lane & 3;
#pragma unroll
    for (int mi = 0; mi < 4; mi++) {
#pragma unroll
        for (int nj = 0; nj < 4; nj++) {
            int col = n0 + wn + nj * 8 + tig * 2;
            float bx = 0.f, by = 0.f;
            if (bias) { bx = bias[col]; by = bias[col + 1]; }
#pragma unroll
            for (int h = 0; h < 2; h++) {
                int row = m0 + wm + mi * 16 + group + h * 8;
                if (row >= Mreal) continue;
                float c0 = acc[mi][nj][h * 2 + 0] + bx;
                float c1 = acc[mi][nj][h * 2 + 1] + by;
                if (MODE == 2) {
                    float2 rr = *(const float2*)(res + (size_t)row * resStride + col);
                    c0 += rr.x; c1 += rr.y;
                }
                if (MODE == 3) {
                    __half2 hp;
                    hp.x = __float2half(qgelu(c0));
                    hp.y = __float2half(qgelu(c1));
                    *(__half2*)((__half*)Cout + (size_t)row * N + col) = hp;
                } else if (MODE == 1) {
                    __half2 hp;
                    hp.x = __float2half(c0);
                    hp.y = __float2half(c1);
                    *(__half2*)((__half*)Cout + (size_t)row * N + col) = hp;
                } else {
                    *(float2*)((float*)Cout + (size_t)row * N + col) = make_float2(c0, c1);
                }
            }
        }
    }
}

// ======== tensor-core attention: fp16 qkv input; mma QK + PV ========
#define QS 72
#define VTS 216
#define NT 208
#define ATTN_SMEM_BYTES ((NT*QS + NT*QS + 64*VTS)*2)   // 87552
__global__ __launch_bounds__(256, 1)
void attn_kernel(const __half* __restrict__ qkv, __half* __restrict__ o) {
    extern __shared__ __half ash[];
    __half* sQ  = ash;
    __half* sK  = sQ + NT * QS;
    __half* sVT = sK + NT * QS;
    int bh = blockIdx.x;
    int b = bh / Hn, hh = bh % Hn;
    int tid = threadIdx.x;
    size_t base = (size_t)b * STOK * NQKV + (size_t)hh * DHd;

    for (int idx = tid; idx < 3 * 32; idx += 256) {
        int r = 205 + idx / 32, d2 = idx % 32;
        *(__half2*)(sQ + r * QS + 2 * d2) = __floats2half2_rn(0.f, 0.f);
        *(__half2*)(sK + r * QS + 2 * d2) = __floats2half2_rn(0.f, 0.f);
    }
    for (int idx = tid; idx < 64 * 3; idx += 256) {
        int d = idx / 3, t = 205 + idx % 3;
        sVT[d * VTS + t] = __float2half(0.f);
    }
    for (int idx = tid; idx < STOK * 32; idx += 256) {
        int j = idx >> 5, d2 = idx & 31;
        const __half2* rp = (const __half2*)(qkv + base + (size_t)j * NQKV) + d2;
        __half2 qq = rp[0];
        __half2 kk = rp[384];
        __half2 vv = rp[768];
        *(__half2*)(sQ + j * QS + 2 * d2) = qq;
        *(__half2*)(sK + j * QS + 2 * d2) = kk;
        sVT[(2 * d2) * VTS + j]     = __low2half(vv);
        sVT[(2 * d2 + 1) * VTS + j] = __high2half(vv);
    }
    __syncthreads();

    int warp = tid >> 5, lane = tid & 31;
    int group = lane >> 2, tig = lane & 3;
    int rrow = lane & 15, khalf = (lane >> 4) << 3;

    for (int qt = warp; qt < 13; qt += 8) {
        float S[26][4];
#pragma unroll
        for (int f = 0; f < 26; f++)
#pragma unroll
            for (int e = 0; e < 4; e++) S[f][e] = 0.f;

#pragma unroll
        for (int kt = 0; kt < 4; kt++) {
            unsigned aq[4];
            ldm4(aq, sQ + (qt * 16 + rrow) * QS + kt * 16 + khalf);
#pragma unroll
            for (int nt = 0; nt < 13; nt++) {
                unsigned kb[4];
                ldm4(kb, sK + (nt * 16 + rrow) * QS + kt * 16 + khalf);
                mma16816(S[2 * nt],     aq, kb[0], kb[2]);
                mma16816(S[2 * nt + 1], aq, kb[1], kb[3]);
            }
        }

        float mx0 = -1e30f, mx1 = -1e30f;
#pragma unroll
        for (int f = 0; f < 26; f++) {
            int c0 = f * 8 + 2 * tig;
            if (c0 < STOK)     { mx0 = fmaxf(mx0, S[f][0]); mx1 = fmaxf(mx1, S[f][2]); }
            if (c0 + 1 < STOK) { mx0 = fmaxf(mx0, S[f][1]); mx1 = fmaxf(mx1, S[f][3]); }
        }
        mx0 = fmaxf(mx0, __shfl_xor_sync(0xffffffffu, mx0, 1));
        mx0 = fmaxf(mx0, __shfl_xor_sync(0xffffffffu, mx0, 2));
        mx1 = fmaxf(mx1, __shfl_xor_sync(0xffffffffu, mx1, 1));
        mx1 = fmaxf(mx1, __shfl_xor_sync(0xffffffffu, mx1, 2));

        float sum0 = 0.f, sum1 = 0.f;
        unsigned Pg[26], Pg8[26];
#pragma unroll
        for (int f = 0; f < 26; f++) {
            int c0 = f * 8 + 2 * tig;
            float e0 = (c0 < STOK)     ? __expf(S[f][0] - mx0) : 0.f;
            float e1 = (c0 + 1 < STOK) ? __expf(S[f][1] - mx0) : 0.f;
            float e2 = (c0 < STOK)     ? __expf(S[f][2] - mx1) : 0.f;
            float e3 = (c0 + 1 < STOK) ? __expf(S[f][3] - mx1) : 0.f;
            sum0 += e0 + e1;
            sum1 += e2 + e3;
            Pg[f]  = packh2(e0, e1);
            Pg8[f] = packh2(e2, e3);
        }
        sum0 += __shfl_xor_sync(0xffffffffu, sum0, 1);
        sum0 += __shfl_xor_sync(0xffffffffu, sum0, 2);
        sum1 += __shfl_xor_sync(0xffffffffu, sum1, 1);
        sum1 += __shfl_xor_sync(0xffffffffu, sum1, 2);
        float inv0 = 1.f / sum0, inv1 = 1.f / sum1;

        float O[8][4];
#pragma unroll
        for (int f = 0; f < 8; f++)
#pragma unroll
            for (int e = 0; e < 4; e++) O[f][e] = 0.f;

#pragma unroll
        for (int kt = 0; kt < 13; kt++) {
            unsigned ap[4] = {Pg[2 * kt], Pg8[2 * kt], Pg[2 * kt + 1], Pg8[2 * kt + 1]};
#pragma unroll
            for (int vd = 0; vd < 4; vd++) {
                unsigned vb[4];
                ldm4(vb, sVT + (vd * 16 + rrow) * VTS + kt * 16 + khalf);
                mma16816(O[2 * vd],     ap, vb[0], vb[2]);
                mma16816(O[2 * vd + 1], ap, vb[1], vb[3]);
            }
        }

        int q0 = qt * 16 + group;
        int q1 = q0 + 8;
#pragma unroll
        for (int nt = 0; nt < 8; nt++) {
            int col = hh * DHd + nt * 8 + 2 * tig;
            if (q0 < STOK) {
                __half2 hp = __floats2half2_rn(O[nt][0] * inv0, O[nt][1] * inv0);
                *(__half2*)(o + (size_t)(b * STOK + q0) * Dm + col) = hp;
            }
            if (q1 < STOK) {
                __half2 hp = __floats2half2_rn(O[nt][2] * inv1, O[nt][3] * inv1);
                *(__half2*)(o + (size_t)(b * STOK + q1) * Dm + col) = hp;
            }
        }
    }
}

// ---------------- host orchestration ----------------
extern "C" void kernel_launch(void* const* d_in, const int* in_sizes, int n_in,
                              void* d_out, int out_size) {
    const float* image   = (const float*)d_in[0];
    const float* gprompt = (const float*)d_in[1];
    const float* patch_w = (const float*)d_in[2];
    const float* cls_emb = (const float*)d_in[3];
    const float* pos_emb = (const float*)d_in[4];
    const float* pre_g   = (const float*)d_in[5];
    const float* pre_b   = (const float*)d_in[6];
    const float* ln1_g   = (const float*)d_in[7];
    const float* ln1_b   = (const float*)d_in[8];
    const float* qw      = (const float*)d_in[9];
    const float* qb      = (const float*)d_in[10];
    const float* kw      = (const float*)d_in[11];
    const float* kb      = (const float*)d_in[12];
    const float* vw      = (const float*)d_in[13];
    const float* vb      = (const float*)d_in[14];
    const float* ow      = (const float*)d_in[15];
    const float* ob      = (const float*)d_in[16];
    const float* ln2_g   = (const float*)d_in[17];
    const float* ln2_b   = (const float*)d_in[18];
    const float* fc1_w   = (const float*)d_in[19];
    const float* fc1_b   = (const float*)d_in[20];
    const float* fc2_w   = (const float*)d_in[21];
    const float* fc2_b   = (const float*)d_in[22];
    const float* post_g  = (const float*)d_in[23];
    const float* post_b  = (const float*)d_in[24];
    float* out = (float*)d_out;

    float *x, *feat, *bqkv;
    __half *qkvh, *ae1, *ae2, *wqkvd, *wod, *w1d, *w2d, *wpd;
    cudaGetSymbolAddress((void**)&x,    g_x);
    cudaGetSymbolAddress((void**)&feat, g_feat);
    cudaGetSymbolAddress((void**)&qkvh, g_qkvh);
    cudaGetSymbolAddress((void**)&bqkv, g_bqkv);
    cudaGetSymbolAddress((void**)&ae1,  g_ae1);
    cudaGetSymbolAddress((void**)&ae2,  g_ae2);
    cudaGetSymbolAddress((void**)&wqkvd, g_wqkv);
    cudaGetSymbolAddress((void**)&wod,  g_wo);
    cudaGetSymbolAddress((void**)&w1d,  g_w1);
    cudaGetSymbolAddress((void**)&w2d,  g_w2);
    cudaGetSymbolAddress((void**)&wpd,  g_wp);

    cudaFuncSetAttribute(attn_kernel, cudaFuncAttributeMaxDynamicSharedMemorySize, ATTN_SMEM_BYTES);
    cudaFuncSetAttribute(bgemm_kernel<0>, cudaFuncAttributeMaxDynamicSharedMemorySize, GSM);
    cudaFuncSetAttribute(bgemm_kernel<1>, cudaFuncAttributeMaxDynamicSharedMemorySize, GSM);
    cudaFuncSetAttribute(bgemm_kernel<2>, cudaFuncAttributeMaxDynamicSharedMemorySize, GSM);
    cudaFuncSetAttribute(bgemm_kernel<3>, cudaFuncAttributeMaxDynamicSharedMemorySize, GSM);

    // --- preamble; position #4 (1-based) = conv GEMM for ncu capture ---
    {
        long long n;
        n = (long long)Dm * Dm / 4;                                        // 1
        wconv_kernel<<<(unsigned)((n + 255) / 256), 256>>>(patch_w, wpd, n);
        im2col_kernel<<<(MPATCH * Dm / 2 + 255) / 256, 256>>>(image, ae1);  // 2
        bconv_qkv_kernel<<<(Lnum * NQKV + 255) / 256, 256>>>(qb, kb, vb, bqkv); // 3
        // 4: conv GEMM  <- ncu capture target
        bgemm_kernel<0><<<dim3(Dm / 128, MPATCH / 128), 256, GSM>>>(
            ae1, wpd, nullptr, nullptr, feat, Dm, Dm, MPATCH, 0);
        n = (long long)Lnum * NQKV * (Dm / 4);                              // 5
        wconv_qkv_kernel<<<(unsigned)((n + 255) / 256), 256>>>(qw, kw, vw, wqkvd);
        assemble_kernel<<<(MTOK * Dm / 4 + 255) / 256, 256>>>(feat, cls_emb, pos_emb, gprompt, x); // 6
        ln_kernel<0><<<MTOK, 256>>>(x, pre_g, pre_b, x, Dm, Dm, nullptr, 0); // 7
        n = (long long)Lnum * Dm * Dm / 4;                                  // 8
        wconv_kernel<<<(unsigned)((n + 255) / 256), 256>>>(ow, wod, n);
        n = (long long)Lnum * FFd * Dm / 4;                                 // 9
        wconv_kernel<<<(unsigned)((n + 255) / 256), 256>>>(fc1_w, w1d, n);
        n = (long long)Lnum * Dm * FFd / 4;                                 // 10
        wconv_kernel<<<(unsigned)((n + 255) / 256), 256>>>(fc2_w, w2d, n);
    }

    dim3 g768(Dm / 128, MPAD / 128);    // (6, 103)
    dim3 gqkv(NQKV / 128, MPAD / 128);  // (18, 103)
    dim3 gff(FFd / 128, MPAD / 128);    // (24, 103)

    for (int l = 0; l < Lnum; l++) {
        // attention (ln1 folds the prompt replacement for l>0)
        ln_kernel<1><<<MTOK, 256>>>(x, ln1_g + (size_t)l * Dm, ln1_b + (size_t)l * Dm,
                                    ae1, Dm, 0, gprompt, l);
        bgemm_kernel<1><<<gqkv, 256, GSM>>>(
            ae1, wqkvd + (size_t)l * NQKV * Dm, bqkv + (size_t)l * NQKV,
            nullptr, qkvh, Dm, NQKV, MTOK, 0);
        attn_kernel<<<Bsz * Hn, 256, ATTN_SMEM_BYTES>>>(qkvh, ae1);
        bgemm_kernel<2><<<g768, 256, GSM>>>(
            ae1, wod + (size_t)l * Dm * Dm, ob + (size_t)l * Dm,
            x, x, Dm, Dm, MTOK, Dm);
        // MLP
        ln_kernel<1><<<MTOK, 256>>>(x, ln2_g + (size_t)l * Dm, ln2_b + (size_t)l * Dm,
                                    ae1, Dm, 0, nullptr, 0);
        bgemm_kernel<3><<<gff, 256, GSM>>>(
            ae1, w1d + (size_t)l * FFd * Dm, fc1_b + (size_t)l * FFd,
            nullptr, ae2, Dm, FFd, MTOK, 0);
        bgemm_kernel<2><<<g768, 256, GSM>>>(
            ae2, w2d + (size_t)l * Dm * FFd, fc2_b + (size_t)l * Dm,
            x, x, FFd, Dm, MTOK, Dm);
    }

    ln_kernel<0><<<Bsz, 256>>>(x, post_g, post_b, out, STOK * Dm, Dm, nullptr, 0);
}

// round 16
// speedup vs baseline: 1.0570x; 1.0218x over previous
#include <cuda_runtime.h>
#include <cuda_fp16.h>
#include <math.h>
#include <stdint.h>

// ---------------- problem constants ----------------
#define Bsz    64
#define Dm     768
#define Hn     12
#define DHd    64
#define Lnum   12
#define FFd    3072
#define NPRn   8
#define STOK   205
#define NPATCH 196
#define MTOK   (Bsz*STOK)     // 13120
#define MPATCH (Bsz*NPATCH)   // 12544 = 98*128
#define MPAD   13184          // 103*128 >= MTOK
#define NQKV   2304           // fused q|k|v output width

// ---------------- static device scratch ----------------
__device__ float  g_x[MPAD*Dm];
__device__ float  g_feat[MPATCH*Dm];              // conv output fp32
__device__ __half g_qkvh[(size_t)MPAD*NQKV];      // packed q|k|v fp16
__device__ float  g_bqkv[(size_t)Lnum*NQKV];
__device__ __half g_ae1[(size_t)MPAD*Dm];         // fp16 activations (K=768 GEMMs)
__device__ __half g_ae2[(size_t)MPAD*FFd];        // fp16 MLP hidden
__device__ __half g_wqkv[(size_t)Lnum*NQKV*Dm];
__device__ __half g_wo[(size_t)Lnum*Dm*Dm];
__device__ __half g_w1[(size_t)Lnum*FFd*Dm];
__device__ __half g_w2[(size_t)Lnum*Dm*FFd];
__device__ __half g_wp[(size_t)Dm*Dm];

// ---------------- helpers ----------------
__device__ __forceinline__ float qgelu(float x) {
    return x / (1.f + expf(-1.702f * x));
}
__device__ __forceinline__ void cp16(void* s, const void* g) {
    unsigned sa = (unsigned)__cvta_generic_to_shared(s);
    asm volatile("cp.async.ca.shared.global [%0], [%1], 16;\n" :: "r"(sa), "l"(g));
}
__device__ __forceinline__ void ldm4(unsigned* r, const __half* p) {
    unsigned s = (unsigned)__cvta_generic_to_shared(p);
    asm volatile("ldmatrix.sync.aligned.m8n8.x4.shared.b16 {%0,%1,%2,%3}, [%4];"
                 : "=r"(r[0]), "=r"(r[1]), "=r"(r[2]), "=r"(r[3]) : "r"(s));
}
__device__ __forceinline__ void mma16816(float* d, const unsigned* a, unsigned b0, unsigned b1) {
    asm volatile("mma.sync.aligned.m16n8k16.row.col.f32.f16.f16.f32 "
                 "{%0,%1,%2,%3}, {%4,%5,%6,%7}, {%8,%9}, {%0,%1,%2,%3};"
                 : "+f"(d[0]), "+f"(d[1]), "+f"(d[2]), "+f"(d[3])
                 : "r"(a[0]), "r"(a[1]), "r"(a[2]), "r"(a[3]), "r"(b0), "r"(b1));
}
__device__ __forceinline__ unsigned packh2(float a, float b) {
    __half2 h = __floats2half2_rn(a, b);
    return *(unsigned*)&h;
}

// ---------------- weight conversion: fp32 -> fp16 (vectorized x4) ----------------
__global__ __launch_bounds__(256) void wconv_kernel(const float* __restrict__ src,
                                                    __half* __restrict__ dst,
                                                    long long total4) {
    long long idx = (long long)blockIdx.x * 256 + threadIdx.x;
    if (idx >= total4) return;
    float4 v = ((const float4*)src)[idx];
    uint2 o;
    o.x = packh2(v.x, v.y);
    o.y = packh2(v.z, v.w);
    ((uint2*)dst)[idx] = o;
}

// ---------------- fused QKV weight conversion (scale folded into q rows, x4) -----------
__global__ __launch_bounds__(256) void wconv_qkv_kernel(const float* __restrict__ qw,
                                                        const float* __restrict__ kw,
                                                        const float* __restrict__ vw,
                                                        __half* __restrict__ dst) {
    long long idx = (long long)blockIdx.x * 256 + threadIdx.x;   // in float4 units
    if (idx >= (long long)Lnum * NQKV * (Dm / 4)) return;
    int k4 = (int)(idx % (Dm / 4));
    long long rowall = idx / (Dm / 4);
    int rr = (int)(rowall % NQKV);
    int l  = (int)(rowall / NQKV);
    float4 v;
    float sc = 1.f;
    if (rr < 768) {
        v = *(const float4*)(qw + (((size_t)l * Dm + rr) * Dm) + 4 * k4);
        sc = 0.125f;
    } else if (rr < 1536) {
        v = *(const float4*)(kw + (((size_t)l * Dm + (rr - 768)) * Dm) + 4 * k4);
    } else {
        v = *(const float4*)(vw + (((size_t)l * Dm + (rr - 1536)) * Dm) + 4 * k4);
    }
    uint2 o;
    o.x = packh2(v.x * sc, v.y * sc);
    o.y = packh2(v.z * sc, v.w * sc);
    ((uint2*)dst)[idx] = o;
}

__global__ __launch_bounds__(256) void bconv_qkv_kernel(const float* __restrict__ qb,
                                                        const float* __restrict__ kb,
                                                        const float* __restrict__ vb,
                                                        float* __restrict__ out) {
    int idx = blockIdx.x * 256 + threadIdx.x;
    if (idx >= Lnum * NQKV) return;
    int rr = idx % NQKV, l = idx / NQKV;
    float v;
    if (rr < 768)       v = qb[l * Dm + rr] * 0.125f;
    else if (rr < 1536) v = kb[l * Dm + (rr - 768)];
    else                v = vb[l * Dm + (rr - 1536)];
    out[idx] = v;
}

// ---------------- im2col fp16 (x2): image -> ae1 [MPATCH, 768] ----------------
__global__ __launch_bounds__(256) void im2col_kernel(const float* __restrict__ img,
                                                     __half* __restrict__ out) {
    int idx = blockIdx.x * 256 + threadIdx.x;     // in pairs
    if (idx >= MPATCH * Dm / 2) return;
    int k = (idx % (Dm / 2)) * 2;
    int m = idx / (Dm / 2);
    int b = m / NPATCH, p = m % NPATCH;
    int py = p / 14, px = p % 14;
    int c = k >> 8, i = (k >> 4) & 15, j = k & 15;
    float2 v = *(const float2*)(img + (((size_t)b * 3 + c) * 224 + (py * 16 + i)) * 224
                                + (px * 16 + j));
    ((unsigned*)out)[idx] = packh2(v.x, v.y);
}

// ---------------- assemble (x4) ----------------
__global__ __launch_bounds__(256) void assemble_kernel(const float* __restrict__ feat,
                                                       const float* __restrict__ cls,
                                                       const float* __restrict__ pos,
                                                       const float* __restrict__ gp,
                                                       float* __restrict__ x) {
    int idx = blockIdx.x * blockDim.x + threadIdx.x;   // in float4 units
    if (idx >= MTOK * Dm / 4) return;
    int d = (idx % (Dm / 4)) * 4;
    int s = (idx / (Dm / 4)) % STOK;
    int b = idx / ((Dm / 4) * STOK);
    float4 v;
    if (s == 0) {
        float4 cv = *(const float4*)(cls + d);
        float4 pv = *(const float4*)(pos + d);
        v = make_float4(cv.x + pv.x, cv.y + pv.y, cv.z + pv.z, cv.w + pv.w);
    } else if (s < 197) {
        float4 fv = *(const float4*)(feat + ((size_t)(b * NPATCH + s - 1)) * Dm + d);
        float4 pv = *(const float4*)(pos + (size_t)s * Dm + d);
        v = make_float4(fv.x + pv.x, fv.y + pv.y, fv.z + pv.z, fv.w + pv.w);
    } else {
        v = *(const float4*)(gp + (((size_t)b * Lnum + 0) * NPRn + (s - 197)) * Dm + d);
    }
    ((float4*)x)[idx] = v;
}

// ---------------- LayerNorm: one row per warp, 8 rows/block (no block barrier) ----------
// EXPOUT=0: fp32 out (out_stride). EXPOUT=1: fp16 out (stride 768).
// If gp != nullptr && layer>0: rows with s>=197 read the layer's prompt instead of x
// and write the raw prompt back into x (residual stream).
template <int EXPOUT>
__global__ __launch_bounds__(256) void ln_kernel(float* __restrict__ x,
                                                 const float* __restrict__ g,
                                                 const float* __restrict__ bb,
                                                 void* __restrict__ outp,
                                                 int in_stride, int out_stride,
                                                 const float* __restrict__ gp, int layer,
                                                 int nrows) {
    int warp = threadIdx.x >> 5, lane = threadIdx.x & 31;
    int row = blockIdx.x * 8 + warp;
    if (row >= nrows) return;
    const float* src = x + (size_t)row * in_stride;
    bool isPrompt = false;
    if (EXPOUT && gp != nullptr && layer > 0) {
        int s = row % STOK;
        if (s >= 197) {
            int b = row / STOK;
            src = gp + (((size_t)b * Lnum + layer) * NPRn + (s - 197)) * Dm;
            isPrompt = true;
        }
    }
    float4 v[6];
#pragma unroll
    for (int k = 0; k < 6; k++)
        v[k] = *(const float4*)(src + (k * 32 + lane) * 4);
    if (isPrompt) {
        float* xr = x + (size_t)row * in_stride;
#pragma unroll
        for (int k = 0; k < 6; k++)
            *(float4*)(xr + (k * 32 + lane) * 4) = v[k];
    }
    float s = 0.f, q = 0.f;
#pragma unroll
    for (int k = 0; k < 6; k++) {
        s += v[k].x + v[k].y + v[k].z + v[k].w;
        q += v[k].x * v[k].x + v[k].y * v[k].y + v[k].z * v[k].z + v[k].w * v[k].w;
    }
#pragma unroll
    for (int off = 16; off; off >>= 1) {
        s += __shfl_xor_sync(0xffffffffu, s, off);
        q += __shfl_xor_sync(0xffffffffu, q, off);
    }
    float mean = s * (1.f / 768.f);
    float inv  = rsqrtf(q * (1.f / 768.f) - mean * mean + 1e-5f);
#pragma unroll
    for (int k = 0; k < 6; k++) {
        int d = (k * 32 + lane) * 4;
        float4 gv = *(const float4*)(g + d);
        float4 bv = *(const float4*)(bb + d);
        float y0 = (v[k].x - mean) * inv * gv.x + bv.x;
        float y1 = (v[k].y - mean) * inv * gv.y + bv.y;
        float y2 = (v[k].z - mean) * inv * gv.z + bv.z;
        float y3 = (v[k].w - mean) * inv * gv.w + bv.w;
        if (EXPOUT) {
            uint2 o;
            o.x = packh2(y0, y1);
            o.y = packh2(y2, y3);
            *(uint2*)((__half*)outp + (size_t)row * Dm + d) = o;
        } else {
            *(float4*)((float*)outp + (size_t)row * out_stride + d) =
                make_float4(y0, y1, y2, y3);
        }
    }
}

// ======== fp16 HMMA GEMM (proven config): C[M,N] = A[M,Kp] @ W[N,Kp]^T ========
// BM=128, BN=128, warp 64x32, 256 thr, 2 CTA/SM, 3-stage cp.async, K-tile 32.
// MODE 0: +bias fp32; 1: +bias fp16; 2: +bias+res fp32; 3: quick_gelu(+bias) fp16
#define BKt 32
#define SKS 40
#define STG (128*SKS)
#define GSM (6*STG*2)    // 61440 bytes

template <int MODE>
__global__ __launch_bounds__(256, 2)
void bgemm_kernel(const __half* __restrict__ A, const __half* __restrict__ W,
                  const float* __restrict__ bias, const float* __restrict__ res,
                  void* __restrict__ Cout, int Kp, int N, int Mreal, int resStride) {
    extern __shared__ __half smem[];
    __half* sAb = smem;
    __half* sBb = smem + 3 * STG;

    int tid = threadIdx.x, lane = tid & 31, warp = tid >> 5;
    int m0 = blockIdx.y * 128, n0 = blockIdx.x * 128;
    int wm = (warp >> 2) * 64, wn = (warp & 3) * 32;
    int lrow = tid >> 2, lko = (tid & 3) << 3;

    const __half* Ag0 = A + (size_t)(m0 + lrow) * Kp + lko;
    const __half* Ag1 = A + (size_t)(m0 + lrow + 64) * Kp + lko;
    const __half* Bg0 = W + (size_t)(n0 + lrow) * Kp + lko;
    const __half* Bg1 = W + (size_t)(n0 + lrow + 64) * Kp + lko;

    float acc[4][4][4];
#pragma unroll
    for (int i = 0; i < 4; i++)
#pragma unroll
        for (int j = 0; j < 4; j++)
#pragma unroll
            for (int e = 0; e < 4; e++) acc[i][j][e] = 0.f;

    auto load_stage = [&](int st, int k0) {
        __half* a = sAb + st * STG + lrow * SKS + lko;
        __half* b = sBb + st * STG + lrow * SKS + lko;
        cp16(a,            Ag0 + k0);
        cp16(a + 64 * SKS, Ag1 + k0);
        cp16(b,            Bg0 + k0);
        cp16(b + 64 * SKS, Bg1 + k0);
        asm volatile("cp.async.commit_group;\n" ::: "memory");
    };

    int nk = Kp / BKt;
    load_stage(0, 0);
    load_stage(1, BKt);

    int cs = 0, ls = 2;
    for (int t = 0; t < nk; t++) {
        if (t + 1 < nk) asm volatile("cp.async.wait_group 1;\n" ::: "memory");
        else            asm volatile("cp.async.wait_group 0;\n" ::: "memory");
        __syncthreads();
        if (t + 2 < nk) load_stage(ls, (t + 2) * BKt);
        ls = (ls == 2) ? 0 : ls + 1;

        const __half* as = sAb + cs * STG;
        const __half* bs = sBb + cs * STG;
        cs = (cs == 2) ? 0 : cs + 1;
#pragma unroll
        for (int kk = 0; kk < 2; kk++) {
            int kof = kk * 16 + ((lane >> 4) << 3);
            int rrow = lane & 15;
            unsigned ar[4][4];
#pragma unroll
            for (int mi = 0; mi < 4; mi++)
                ldm4(ar[mi], &as[(wm + mi * 16 + rrow) * SKS + kof]);
            unsigned br[2][4];
#pragma unroll
            for (int p = 0; p < 2; p++)
                ldm4(br[p], &bs[(wn + p * 16 + rrow) * SKS + kof]);
#pragma unroll
            for (int mi = 0; mi < 4; mi++)
#pragma unroll
                for (int nj = 0; nj < 4; nj++)
                    mma16816(acc[mi][nj], ar[mi], br[nj >> 1][nj & 1], br[nj >> 1][(nj & 1) + 2]);
        }
    }

    int group = lane >> 2, tig = lane & 3;
#pragma unroll
    for (int mi = 0; mi < 4; mi++) {
#pragma unroll
        for (int nj = 0; nj < 4; nj++) {
            int col = n0 + wn + nj * 8 + tig * 2;
            float bx = 0.f, by = 0.f;
            if (bias) { bx = bias[col]; by = bias[col + 1]; }
#pragma unroll
            for (int h = 0; h < 2; h++) {
                int row = m0 + wm + mi * 16 + group + h * 8;
                if (row >= Mreal) continue;
                float c0 = acc[mi][nj][h * 2 + 0] + bx;
                float c1 = acc[mi][nj][h * 2 + 1] + by;
                if (MODE == 2) {
                    float2 rr = *(const float2*)(res + (size_t)row * resStride + col);
                    c0 += rr.x; c1 += rr.y;
                }
                if (MODE == 3) {
                    __half2 hp;
                    hp.x = __float2half(qgelu(c0));
                    hp.y = __float2half(qgelu(c1));
                    *(__half2*)((__half*)Cout + (size_t)row * N + col) = hp;
                } else if (MODE == 1) {
                    __half2 hp;
                    hp.x = __float2half(c0);
                    hp.y = __float2half(c1);
                    *(__half2*)((__half*)Cout + (size_t)row * N + col) = hp;
                } else {
                    *(float2*)((float*)Cout + (size_t)row * N + col) = make_float2(c0, c1);
                }
            }
        }
    }
}

// ======== tensor-core attention: fp16 qkv input; mma QK + PV ========
#define QS 72
#define VTS 216
#define NT 208
#define ATTN_SMEM_BYTES ((NT*QS + NT*QS + 64*VTS)*2)   // 87552
__global__ __launch_bounds__(256, 1)
void attn_kernel(const __half* __restrict__ qkv, __half* __restrict__ o) {
    extern __shared__ __half ash[];
    __half* sQ  = ash;
    __half* sK  = sQ + NT * QS;
    __half* sVT = sK + NT * QS;
    int bh = blockIdx.x;
    int b = bh / Hn, hh = bh % Hn;
    int tid = threadIdx.x;
    size_t base = (size_t)b * STOK * NQKV + (size_t)hh * DHd;

    for (int idx = tid; idx < 3 * 32; idx += 256) {
        int r = 205 + idx / 32, d2 = idx % 32;
        *(__half2*)(sQ + r * QS + 2 * d2) = __floats2half2_rn(0.f, 0.f);
        *(__half2*)(sK + r * QS + 2 * d2) = __floats2half2_rn(0.f, 0.f);
    }
    for (int idx = tid; idx < 64 * 3; idx += 256) {
        int d = idx / 3, t = 205 + idx % 3;
        sVT[d * VTS + t] = __float2half(0.f);
    }
    for (int idx = tid; idx < STOK * 32; idx += 256) {
        int j = idx >> 5, d2 = idx & 31;
        const __half2* rp = (const __half2*)(qkv + base + (size_t)j * NQKV) + d2;
        __half2 qq = rp[0];
        __half2 kk = rp[384];
        __half2 vv = rp[768];
        *(__half2*)(sQ + j * QS + 2 * d2) = qq;
        *(__half2*)(sK + j * QS + 2 * d2) = kk;
        sVT[(2 * d2) * VTS + j]     = __low2half(vv);
        sVT[(2 * d2 + 1) * VTS + j] = __high2half(vv);
    }
    __syncthreads();

    int warp = tid >> 5, lane = tid & 31;
    int group = lane >> 2, tig = lane & 3;
    int rrow = lane & 15, khalf = (lane >> 4) << 3;

    for (int qt = warp; qt < 13; qt += 8) {
        float S[26][4];
#pragma unroll
        for (int f = 0; f < 26; f++)
#pragma unroll
            for (int e = 0; e < 4; e++) S[f][e] = 0.f;

#pragma unroll
        for (int kt = 0; kt < 4; kt++) {
            unsigned aq[4];
            ldm4(aq, sQ + (qt * 16 + rrow) * QS + kt * 16 + khalf);
#pragma unroll
            for (int nt = 0; nt < 13; nt++) {
                unsigned kb[4];
                ldm4(kb, sK + (nt * 16 + rrow) * QS + kt * 16 + khalf);
                mma16816(S[2 * nt],     aq, kb[0], kb[2]);
                mma16816(S[2 * nt + 1], aq, kb[1], kb[3]);
            }
        }

        float mx0 = -1e30f, mx1 = -1e30f;
#pragma unroll
        for (int f = 0; f < 26; f++) {
            int c0 = f * 8 + 2 * tig;
            if (c0 < STOK)     { mx0 = fmaxf(mx0, S[f][0]); mx1 = fmaxf(mx1, S[f][2]); }
            if (c0 + 1 < STOK) { mx0 = fmaxf(mx0, S[f][1]); mx1 = fmaxf(mx1, S[f][3]); }
        }
        mx0 = fmaxf(mx0, __shfl_xor_sync(0xffffffffu, mx0, 1));
        mx0 = fmaxf(mx0, __shfl_xor_sync(0xffffffffu, mx0, 2));
        mx1 = fmaxf(mx1, __shfl_xor_sync(0xffffffffu, mx1, 1));
        mx1 = fmaxf(mx1, __shfl_xor_sync(0xffffffffu, mx1, 2));

        float sum0 = 0.f, sum1 = 0.f;
        unsigned Pg[26], Pg8[26];
#pragma unroll
        for (int f = 0; f < 26; f++) {
            int c0 = f * 8 + 2 * tig;
            float e0 = (c0 < STOK)     ? __expf(S[f][0] - mx0) : 0.f;
            float e1 = (c0 + 1 < STOK) ? __expf(S[f][1] - mx0) : 0.f;
            float e2 = (c0 < STOK)     ? __expf(S[f][2] - mx1) : 0.f;
            float e3 = (c0 + 1 < STOK) ? __expf(S[f][3] - mx1) : 0.f;
            sum0 += e0 + e1;
            sum1 += e2 + e3;
            Pg[f]  = packh2(e0, e1);
            Pg8[f] = packh2(e2, e3);
        }
        sum0 += __shfl_xor_sync(0xffffffffu, sum0, 1);
        sum0 += __shfl_xor_sync(0xffffffffu, sum0, 2);
        sum1 += __shfl_xor_sync(0xffffffffu, sum1, 1);
        sum1 += __shfl_xor_sync(0xffffffffu, sum1, 2);
        float inv0 = 1.f / sum0, inv1 = 1.f / sum1;

        float O[8][4];
#pragma unroll
        for (int f = 0; f < 8; f++)
#pragma unroll
            for (int e = 0; e < 4; e++) O[f][e] = 0.f;

#pragma unroll
        for (int kt = 0; kt < 13; kt++) {
            unsigned ap[4] = {Pg[2 * kt], Pg8[2 * kt], Pg[2 * kt + 1], Pg8[2 * kt + 1]};
#pragma unroll
            for (int vd = 0; vd < 4; vd++) {
                unsigned vb[4];
                ldm4(vb, sVT + (vd * 16 + rrow) * VTS + kt * 16 + khalf);
                mma16816(O[2 * vd],     ap, vb[0], vb[2]);
                mma16816(O[2 * vd + 1], ap, vb[1], vb[3]);
            }
        }

        int q0 = qt * 16 + group;
        int q1 = q0 + 8;
#pragma unroll
        for (int nt = 0; nt < 8; nt++) {
            int col = hh * DHd + nt * 8 + 2 * tig;
            if (q0 < STOK) {
                __half2 hp = __floats2half2_rn(O[nt][0] * inv0, O[nt][1] * inv0);
                *(__half2*)(o + (size_t)(b * STOK + q0) * Dm + col) = hp;
            }
            if (q1 < STOK) {
                __half2 hp = __floats2half2_rn(O[nt][2] * inv1, O[nt][3] * inv1);
                *(__half2*)(o + (size_t)(b * STOK + q1) * Dm + col) = hp;
            }
        }
    }
}

// ---------------- host orchestration ----------------
extern "C" void kernel_launch(void* const* d_in, const int* in_sizes, int n_in,
                              void* d_out, int out_size) {
    const float* image   = (const float*)d_in[0];
    const float* gprompt = (const float*)d_in[1];
    const float* patch_w = (const float*)d_in[2];
    const float* cls_emb = (const float*)d_in[3];
    const float* pos_emb = (const float*)d_in[4];
    const float* pre_g   = (const float*)d_in[5];
    const float* pre_b   = (const float*)d_in[6];
    const float* ln1_g   = (const float*)d_in[7];
    const float* ln1_b   = (const float*)d_in[8];
    const float* qw      = (const float*)d_in[9];
    const float* qb      = (const float*)d_in[10];
    const float* kw      = (const float*)d_in[11];
    const float* kb      = (const float*)d_in[12];
    const float* vw      = (const float*)d_in[13];
    const float* vb      = (const float*)d_in[14];
    const float* ow      = (const float*)d_in[15];
    const float* ob      = (const float*)d_in[16];
    const float* ln2_g   = (const float*)d_in[17];
    const float* ln2_b   = (const float*)d_in[18];
    const float* fc1_w   = (const float*)d_in[19];
    const float* fc1_b   = (const float*)d_in[20];
    const float* fc2_w   = (const float*)d_in[21];
    const float* fc2_b   = (const float*)d_in[22];
    const float* post_g  = (const float*)d_in[23];
    const float* post_b  = (const float*)d_in[24];
    float* out = (float*)d_out;

    float *x, *feat, *bqkv;
    __half *qkvh, *ae1, *ae2, *wqkvd, *wod, *w1d, *w2d, *wpd;
    cudaGetSymbolAddress((void**)&x,    g_x);
    cudaGetSymbolAddress((void**)&feat, g_feat);
    cudaGetSymbolAddress((void**)&qkvh, g_qkvh);
    cudaGetSymbolAddress((void**)&bqkv, g_bqkv);
    cudaGetSymbolAddress((void**)&ae1,  g_ae1);
    cudaGetSymbolAddress((void**)&ae2,  g_ae2);
    cudaGetSymbolAddress((void**)&wqkvd, g_wqkv);
    cudaGetSymbolAddress((void**)&wod,  g_wo);
    cudaGetSymbolAddress((void**)&w1d,  g_w1);
    cudaGetSymbolAddress((void**)&w2d,  g_w2);
    cudaGetSymbolAddress((void**)&wpd,  g_wp);

    cudaFuncSetAttribute(attn_kernel, cudaFuncAttributeMaxDynamicSharedMemorySize, ATTN_SMEM_BYTES);
    cudaFuncSetAttribute(bgemm_kernel<0>, cudaFuncAttributeMaxDynamicSharedMemorySize, GSM);
    cudaFuncSetAttribute(bgemm_kernel<1>, cudaFuncAttributeMaxDynamicSharedMemorySize, GSM);
    cudaFuncSetAttribute(bgemm_kernel<2>, cudaFuncAttributeMaxDynamicSharedMemorySize, GSM);
    cudaFuncSetAttribute(bgemm_kernel<3>, cudaFuncAttributeMaxDynamicSharedMemorySize, GSM);

    // --- preamble; position #4 (1-based) = conv GEMM for ncu capture ---
    {
        long long n;
        n = (long long)Dm * Dm / 4;                                        // 1
        wconv_kernel<<<(unsigned)((n + 255) / 256), 256>>>(patch_w, wpd, n);
        im2col_kernel<<<(MPATCH * Dm / 2 + 255) / 256, 256>>>(image, ae1);  // 2
        bconv_qkv_kernel<<<(Lnum * NQKV + 255) / 256, 256>>>(qb, kb, vb, bqkv); // 3
        // 4: conv GEMM  <- ncu capture target
        bgemm_kernel<0><<<dim3(Dm / 128, MPATCH / 128), 256, GSM>>>(
            ae1, wpd, nullptr, nullptr, feat, Dm, Dm, MPATCH, 0);
        n = (long long)Lnum * NQKV * (Dm / 4);                              // 5
        wconv_qkv_kernel<<<(unsigned)((n + 255) / 256), 256>>>(qw, kw, vw, wqkvd);
        assemble_kernel<<<(MTOK * Dm / 4 + 255) / 256, 256>>>(feat, cls_emb, pos_emb, gprompt, x); // 6
        ln_kernel<0><<<(MTOK + 7) / 8, 256>>>(x, pre_g, pre_b, x, Dm, Dm, nullptr, 0, MTOK); // 7
        n = (long long)Lnum * Dm * Dm / 4;                                  // 8
        wconv_kernel<<<(unsigned)((n + 255) / 256), 256>>>(ow, wod, n);
        n = (long long)Lnum * FFd * Dm / 4;                                 // 9
        wconv_kernel<<<(unsigned)((n + 255) / 256), 256>>>(fc1_w, w1d, n);
        n = (long long)Lnum * Dm * FFd / 4;                                 // 10
        wconv_kernel<<<(unsigned)((n + 255) / 256), 256>>>(fc2_w, w2d, n);
    }

    dim3 g768(Dm / 128, MPAD / 128);    // (6, 103)
    dim3 gqkv(NQKV / 128, MPAD / 128);  // (18, 103)
    dim3 gff(FFd / 128, MPAD / 128);    // (24, 103)
    int lnGrid = (MTOK + 7) / 8;

    for (int l = 0; l < Lnum; l++) {
        // attention (ln1 folds the prompt replacement for l>0)
        ln_kernel<1><<<lnGrid, 256>>>(x, ln1_g + (size_t)l * Dm, ln1_b + (size_t)l * Dm,
                                      ae1, Dm, 0, gprompt, l, MTOK);
        bgemm_kernel<1><<<gqkv, 256, GSM>>>(
            ae1, wqkvd + (size_t)l * NQKV * Dm, bqkv + (size_t)l * NQKV,
            nullptr, qkvh, Dm, NQKV, MTOK, 0);
        attn_kernel<<<Bsz * Hn, 256, ATTN_SMEM_BYTES>>>(qkvh, ae1);
        bgemm_kernel<2><<<g768, 256, GSM>>>(
            ae1, wod + (size_t)l * Dm * Dm, ob + (size_t)l * Dm,
            x, x, Dm, Dm, MTOK, Dm);
        // MLP
        ln_kernel<1><<<lnGrid, 256>>>(x, ln2_g + (size_t)l * Dm, ln2_b + (size_t)l * Dm,
                                      ae1, Dm, 0, nullptr, 0, MTOK);
        bgemm_kernel<3><<<gff, 256, GSM>>>(
            ae1, w1d + (size_t)l * FFd * Dm, fc1_b + (size_t)l * FFd,
            nullptr, ae2, Dm, FFd, MTOK, 0);
        bgemm_kernel<2><<<g768, 256, GSM>>>(
            ae2, w2d + (size_t)l * Dm * FFd, fc2_b + (size_t)l * Dm,
            x, x, FFd, Dm, MTOK, Dm);
    }

    ln_kernel<0><<<(Bsz + 7) / 8, 256>>>(x, post_g, post_b, out, STOK * Dm, Dm,
                                         nullptr, 0, Bsz);
}

// round 17
// speedup vs baseline: 1.1555x; 1.0932x over previous
#include <cuda_runtime.h>
#include <cuda_fp16.h>
#include <math.h>
#include <stdint.h>

// ---------------- problem constants ----------------
#define Bsz    64
#define Dm     768
#define Hn     12
#define DHd    64
#define Lnum   12
#define FFd    3072
#define NPRn   8
#define STOK   205
#define NPATCH 196
#define MTOK   (Bsz*STOK)     // 13120
#define MPATCH (Bsz*NPATCH)   // 12544 = 98*128
#define MPAD   13184          // 103*128 >= MTOK
#define NQKV   2304           // fused q|k|v output width

// ---------------- static device scratch ----------------
__device__ float  g_x[MPAD*Dm];
__device__ float  g_feat[MPATCH*Dm];              // conv output fp32
__device__ __half g_qkvh[(size_t)MPAD*NQKV];      // packed q|k|v fp16
__device__ float  g_bqkv[(size_t)Lnum*NQKV];
__device__ __half g_ae1[(size_t)MPAD*Dm];         // fp16 activations (K=768 GEMMs)
__device__ __half g_ae2[(size_t)MPAD*FFd];        // fp16 MLP hidden
__device__ __half g_wqkv[(size_t)Lnum*NQKV*Dm];
__device__ __half g_wo[(size_t)Lnum*Dm*Dm];
__device__ __half g_w1[(size_t)Lnum*FFd*Dm];
__device__ __half g_w2[(size_t)Lnum*Dm*FFd];
__device__ __half g_wp[(size_t)Dm*Dm];

// ---------------- helpers ----------------
__device__ __forceinline__ float qgelu(float x) {
    return x / (1.f + expf(-1.702f * x));
}
__device__ __forceinline__ void cp16(void* s, const void* g) {
    unsigned sa = (unsigned)__cvta_generic_to_shared(s);
    asm volatile("cp.async.ca.shared.global [%0], [%1], 16;\n" :: "r"(sa), "l"(g));
}
__device__ __forceinline__ void ldm4(unsigned* r, const __half* p) {
    unsigned s = (unsigned)__cvta_generic_to_shared(p);
    asm volatile("ldmatrix.sync.aligned.m8n8.x4.shared.b16 {%0,%1,%2,%3}, [%4];"
                 : "=r"(r[0]), "=r"(r[1]), "=r"(r[2]), "=r"(r[3]) : "r"(s));
}
__device__ __forceinline__ void mma16816(float* d, const unsigned* a, unsigned b0, unsigned b1) {
    asm volatile("mma.sync.aligned.m16n8k16.row.col.f32.f16.f16.f32 "
                 "{%0,%1,%2,%3}, {%4,%5,%6,%7}, {%8,%9}, {%0,%1,%2,%3};"
                 : "+f"(d[0]), "+f"(d[1]), "+f"(d[2]), "+f"(d[3])
                 : "r"(a[0]), "r"(a[1]), "r"(a[2]), "r"(a[3]), "r"(b0), "r"(b1));
}
__device__ __forceinline__ unsigned packh2(float a, float b) {
    __half2 h = __floats2half2_rn(a, b);
    return *(unsigned*)&h;
}

// ---------------- weight conversion: fp32 -> fp16 (vectorized x4) ----------------
__global__ __launch_bounds__(256) void wconv_kernel(const float* __restrict__ src,
                                                    __half* __restrict__ dst,
                                                    long long total4) {
    long long idx = (long long)blockIdx.x * 256 + threadIdx.x;
    if (idx >= total4) return;
    float4 v = ((const float4*)src)[idx];
    uint2 o;
    o.x = packh2(v.x, v.y);
    o.y = packh2(v.z, v.w);
    ((uint2*)dst)[idx] = o;
}

// ---------------- fused QKV weight conversion (scale folded into q rows, x4) -----------
__global__ __launch_bounds__(256) void wconv_qkv_kernel(const float* __restrict__ qw,
                                                        const float* __restrict__ kw,
                                                        const float* __restrict__ vw,
                                                        __half* __restrict__ dst) {
    long long idx = (long long)blockIdx.x * 256 + threadIdx.x;   // in float4 units
    if (idx >= (long long)Lnum * NQKV * (Dm / 4)) return;
    int k4 = (int)(idx % (Dm / 4));
    long long rowall = idx / (Dm / 4);
    int rr = (int)(rowall % NQKV);
    int l  = (int)(rowall / NQKV);
    float4 v;
    float sc = 1.f;
    if (rr < 768) {
        v = *(const float4*)(qw + (((size_t)l * Dm + rr) * Dm) + 4 * k4);
        sc = 0.125f;
    } else if (rr < 1536) {
        v = *(const float4*)(kw + (((size_t)l * Dm + (rr - 768)) * Dm) + 4 * k4);
    } else {
        v = *(const float4*)(vw + (((size_t)l * Dm + (rr - 1536)) * Dm) + 4 * k4);
    }
    uint2 o;
    o.x = packh2(v.x * sc, v.y * sc);
    o.y = packh2(v.z * sc, v.w * sc);
    ((uint2*)dst)[idx] = o;
}

__global__ __launch_bounds__(256) void bconv_qkv_kernel(const float* __restrict__ qb,
                                                        const float* __restrict__ kb,
                                                        const float* __restrict__ vb,
                                                        float* __restrict__ out) {
    int idx = blockIdx.x * 256 + threadIdx.x;
    if (idx >= Lnum * NQKV) return;
    int rr = idx % NQKV, l = idx / NQKV;
    float v;
    if (rr < 768)       v = qb[l * Dm + rr] * 0.125f;
    else if (rr < 1536) v = kb[l * Dm + (rr - 768)];
    else                v = vb[l * Dm + (rr - 1536)];
    out[idx] = v;
}

// ---------------- im2col fp16 (x2): image -> ae1 [MPATCH, 768] ----------------
__global__ __launch_bounds__(256) void im2col_kernel(const float* __restrict__ img,
                                                     __half* __restrict__ out) {
    int idx = blockIdx.x * 256 + threadIdx.x;     // in pairs
    if (idx >= MPATCH * Dm / 2) return;
    int k = (idx % (Dm / 2)) * 2;
    int m = idx / (Dm / 2);
    int b = m / NPATCH, p = m % NPATCH;
    int py = p / 14, px = p % 14;
    int c = k >> 8, i = (k >> 4) & 15, j = k & 15;
    float2 v = *(const float2*)(img + (((size_t)b * 3 + c) * 224 + (py * 16 + i)) * 224
                                + (px * 16 + j));
    ((unsigned*)out)[idx] = packh2(v.x, v.y);
}

// ---------------- assemble (x4) ----------------
__global__ __launch_bounds__(256) void assemble_kernel(const float* __restrict__ feat,
                                                       const float* __restrict__ cls,
                                                       const float* __restrict__ pos,
                                                       const float* __restrict__ gp,
                                                       float* __restrict__ x) {
    int idx = blockIdx.x * blockDim.x + threadIdx.x;   // in float4 units
    if (idx >= MTOK * Dm / 4) return;
    int d = (idx % (Dm / 4)) * 4;
    int s = (idx / (Dm / 4)) % STOK;
    int b = idx / ((Dm / 4) * STOK);
    float4 v;
    if (s == 0) {
        float4 cv = *(const float4*)(cls + d);
        float4 pv = *(const float4*)(pos + d);
        v = make_float4(cv.x + pv.x, cv.y + pv.y, cv.z + pv.z, cv.w + pv.w);
    } else if (s < 197) {
        float4 fv = *(const float4*)(feat + ((size_t)(b * NPATCH + s - 1)) * Dm + d);
        float4 pv = *(const float4*)(pos + (size_t)s * Dm + d);
        v = make_float4(fv.x + pv.x, fv.y + pv.y, fv.z + pv.z, fv.w + pv.w);
    } else {
        v = *(const float4*)(gp + (((size_t)b * Lnum + 0) * NPRn + (s - 197)) * Dm + d);
    }
    ((float4*)x)[idx] = v;
}

// ---------------- LayerNorm: one row per warp, 8 rows/block (no block barrier) ----------
// EXPOUT=0: fp32 out (out_stride). EXPOUT=1: fp16 out (stride 768).
// If gp != nullptr && layer>0: rows with s>=197 read the layer's prompt instead of x
// and write the raw prompt back into x (residual stream).
template <int EXPOUT>
__global__ __launch_bounds__(256) void ln_kernel(float* __restrict__ x,
                                                 const float* __restrict__ g,
                                                 const float* __restrict__ bb,
                                                 void* __restrict__ outp,
                                                 int in_stride, int out_stride,
                                                 const float* __restrict__ gp, int layer,
                                                 int nrows) {
    int warp = threadIdx.x >> 5, lane = threadIdx.x & 31;
    int row = blockIdx.x * 8 + warp;
    if (row >= nrows) return;
    const float* src = x + (size_t)row * in_stride;
    bool isPrompt = false;
    if (EXPOUT && gp != nullptr && layer > 0) {
        int s = row % STOK;
        if (s >= 197) {
            int b = row / STOK;
            src = gp + (((size_t)b * Lnum + layer) * NPRn + (s - 197)) * Dm;
            isPrompt = true;
        }
    }
    float4 v[6];
#pragma unroll
    for (int k = 0; k < 6; k++)
        v[k] = *(const float4*)(src + (k * 32 + lane) * 4);
    if (isPrompt) {
        float* xr = x + (size_t)row * in_stride;
#pragma unroll
        for (int k = 0; k < 6; k++)
            *(float4*)(xr + (k * 32 + lane) * 4) = v[k];
    }
    float s = 0.f, q = 0.f;
#pragma unroll
    for (int k = 0; k < 6; k++) {
        s += v[k].x + v[k].y + v[k].z + v[k].w;
        q += v[k].x * v[k].x + v[k].y * v[k].y + v[k].z * v[k].z + v[k].w * v[k].w;
    }
#pragma unroll
    for (int off = 16; off; off >>= 1) {
        s += __shfl_xor_sync(0xffffffffu, s, off);
        q += __shfl_xor_sync(0xffffffffu, q, off);
    }
    float mean = s * (1.f / 768.f);
    float inv  = rsqrtf(q * (1.f / 768.f) - mean * mean + 1e-5f);
#pragma unroll
    for (int k = 0; k < 6; k++) {
        int d = (k * 32 + lane) * 4;
        float4 gv = *(const float4*)(g + d);
        float4 bv = *(const float4*)(bb + d);
        float y0 = (v[k].x - mean) * inv * gv.x + bv.x;
        float y1 = (v[k].y - mean) * inv * gv.y + bv.y;
        float y2 = (v[k].z - mean) * inv * gv.z + bv.z;
        float y3 = (v[k].w - mean) * inv * gv.w + bv.w;
        if (EXPOUT) {
            uint2 o;
            o.x = packh2(y0, y1);
            o.y = packh2(y2, y3);
            *(uint2*)((__half*)outp + (size_t)row * Dm + d) = o;
        } else {
            *(float4*)((float*)outp + (size_t)row * out_stride + d) =
                make_float4(y0, y1, y2, y3);
        }
    }
}

// ======== fp16 HMMA GEMM: C[M,N] = A[M,Kp] @ W[N,Kp]^T ========
// BM=128, BN=128, warp 64x32, 256 thr, 2 CTA/SM.
// K-tile 64, 2-stage cp.async double buffer: same 64-K lookahead as the old
// 3x32K pipeline, but HALF the __syncthreads / wait_group count per tile.
// SKS=72 -> 144B rows = 9x16B (odd) -> 8 consecutive rows hit 8 distinct 16B
// banks -> ldmatrix phases conflict-free without swizzle.
// MODE 0: +bias fp32; 1: +bias fp16; 2: +bias+res fp32; 3: quick_gelu(+bias) fp16
#define BKt 64
#define SKS 72
#define STG (128*SKS)
#define GSM (4*STG*2)    // 2 stages x (A+B) x 128 x 72 x 2B = 73728 bytes

template <int MODE>
__global__ __launch_bounds__(256, 2)
void bgemm_kernel(const __half* __restrict__ A, const __half* __restrict__ W,
                  const float* __restrict__ bias, const float* __restrict__ res,
                  void* __restrict__ Cout, int Kp, int N, int Mreal, int resStride) {
    extern __shared__ __half smem[];
    __half* sAb = smem;             // 2 * STG
    __half* sBb = smem + 2 * STG;   // 2 * STG

    int tid = threadIdx.x, lane = tid & 31, warp = tid >> 5;
    int m0 = blockIdx.y * 128, n0 = blockIdx.x * 128;
    int wm = (warp >> 2) * 64, wn = (warp & 3) * 32;
    int lrow = tid >> 3;            // 0..31
    int lko  = (tid & 7) << 3;      // 0..56 halfs (16B chunks)

    const __half* Ag = A + (size_t)(m0 + lrow) * Kp + lko;
    const __half* Bg = W + (size_t)(n0 + lrow) * Kp + lko;

    float acc[4][4][4];
#pragma unroll
    for (int i = 0; i < 4; i++)
#pragma unroll
        for (int j = 0; j < 4; j++)
#pragma unroll
            for (int e = 0; e < 4; e++) acc[i][j][e] = 0.f;

    auto load_stage = [&](int st, int k0) {
        __half* a = sAb + st * STG + lrow * SKS + lko;
        __half* b = sBb + st * STG + lrow * SKS + lko;
#pragma unroll
        for (int r = 0; r < 4; r++) {
            cp16(a + (32 * r) * SKS, Ag + (size_t)(32 * r) * Kp + k0);
            cp16(b + (32 * r) * SKS, Bg + (size_t)(32 * r) * Kp + k0);
        }
        asm volatile("cp.async.commit_group;\n" ::: "memory");
    };

    int nk = Kp >> 6;      // K-64 iterations
    load_stage(0, 0);

    for (int t = 0; t < nk; t++) {
        asm volatile("cp.async.wait_group 0;\n" ::: "memory");
        __syncthreads();   // stage-t bytes visible to all; compute t-1 fully drained
        if (t + 1 < nk) load_stage((t + 1) & 1, (t + 1) << 6);

        const __half* as = sAb + (t & 1) * STG;
        const __half* bs = sBb + (t & 1) * STG;
#pragma unroll
        for (int kk = 0; kk < 4; kk++) {
            int kof = kk * 16 + ((lane >> 4) << 3);
            int rrow = lane & 15;
            unsigned ar[4][4];
#pragma unroll
            for (int mi = 0; mi < 4; mi++)
                ldm4(ar[mi], &as[(wm + mi * 16 + rrow) * SKS + kof]);
            unsigned br[2][4];
#pragma unroll
            for (int p = 0; p < 2; p++)
                ldm4(br[p], &bs[(wn + p * 16 + rrow) * SKS + kof]);
#pragma unroll
            for (int mi = 0; mi < 4; mi++)
#pragma unroll
                for (int nj = 0; nj < 4; nj++)
                    mma16816(acc[mi][nj], ar[mi], br[nj >> 1][nj & 1], br[nj >> 1][(nj & 1) + 2]);
        }
    }

    int group = lane >> 2, tig = lane & 3;
#pragma unroll
    for (int mi = 0; mi < 4; mi++) {
#pragma unroll
        for (int nj = 0; nj < 4; nj++) {
            int col = n0 + wn + nj * 8 + tig * 2;
            float bx = 0.f, by = 0.f;
            if (bias) { bx = bias[col]; by = bias[col + 1]; }
#pragma unroll
            for (int h = 0; h < 2; h++) {
                int row = m0 + wm + mi * 16 + group + h * 8;
                if (row >= Mreal) continue;
                float c0 = acc[mi][nj][h * 2 + 0] + bx;
                float c1 = acc[mi][nj][h * 2 + 1] + by;
                if (MODE == 2) {
                    float2 rr = *(const float2*)(res + (size_t)row * resStride + col);
                    c0 += rr.x; c1 += rr.y;
                }
                if (MODE == 3) {
                    __half2 hp;
                    hp.x = __float2half(qgelu(c0));
                    hp.y = __float2half(qgelu(c1));
                    *(__half2*)((__half*)Cout + (size_t)row * N + col) = hp;
                } else if (MODE == 1) {
                    __half2 hp;
                    hp.x = __float2half(c0);
                    hp.y = __float2half(c1);
                    *(__half2*)((__half*)Cout + (size_t)row * N + col) = hp;
                } else {
                    *(float2*)((float*)Cout + (size_t)row * N + col) = make_float2(c0, c1);
                }
            }
        }
    }
}

// ======== tensor-core attention: fp16 qkv input; mma QK + PV ========
#define QS 72
#define VTS 216
#define NT 208
#define ATTN_SMEM_BYTES ((NT*QS + NT*QS + 64*VTS)*2)   // 87552
__global__ __launch_bounds__(256, 1)
void attn_kernel(const __half* __restrict__ qkv, __half* __restrict__ o) {
    extern __shared__ __half ash[];
    __half* sQ  = ash;
    __half* sK  = sQ + NT * QS;
    __half* sVT = sK + NT * QS;
    int bh = blockIdx.x;
    int b = bh / Hn, hh = bh % Hn;
    int tid = threadIdx.x;
    size_t base = (size_t)b * STOK * NQKV + (size_t)hh * DHd;

    for (int idx = tid; idx < 3 * 32; idx += 256) {
        int r = 205 + idx / 32, d2 = idx % 32;
        *(__half2*)(sQ + r * QS + 2 * d2) = __floats2half2_rn(0.f, 0.f);
        *(__half2*)(sK + r * QS + 2 * d2) = __floats2half2_rn(0.f, 0.f);
    }
    for (int idx = tid; idx < 64 * 3; idx += 256) {
        int d = idx / 3, t = 205 + idx % 3;
        sVT[d * VTS + t] = __float2half(0.f);
    }
    for (int idx = tid; idx < STOK * 32; idx += 256) {
        int j = idx >> 5, d2 = idx & 31;
        const __half2* rp = (const __half2*)(qkv + base + (size_t)j * NQKV) + d2;
        __half2 qq = rp[0];
        __half2 kk = rp[384];
        __half2 vv = rp[768];
        *(__half2*)(sQ + j * QS + 2 * d2) = qq;
        *(__half2*)(sK + j * QS + 2 * d2) = kk;
        sVT[(2 * d2) * VTS + j]     = __low2half(vv);
        sVT[(2 * d2 + 1) * VTS + j] = __high2half(vv);
    }
    __syncthreads();

    int warp = tid >> 5, lane = tid & 31;
    int group = lane >> 2, tig = lane & 3;
    int rrow = lane & 15, khalf = (lane >> 4) << 3;

    for (int qt = warp; qt < 13; qt += 8) {
        float S[26][4];
#pragma unroll
        for (int f = 0; f < 26; f++)
#pragma unroll
            for (int e = 0; e < 4; e++) S[f][e] = 0.f;

#pragma unroll
        for (int kt = 0; kt < 4; kt++) {
            unsigned aq[4];
            ldm4(aq, sQ + (qt * 16 + rrow) * QS + kt * 16 + khalf);
#pragma unroll
            for (int nt = 0; nt < 13; nt++) {
                unsigned kb[4];
                ldm4(kb, sK + (nt * 16 + rrow) * QS + kt * 16 + khalf);
                mma16816(S[2 * nt],     aq, kb[0], kb[2]);
                mma16816(S[2 * nt + 1], aq, kb[1], kb[3]);
            }
        }

        float mx0 = -1e30f, mx1 = -1e30f;
#pragma unroll
        for (int f = 0; f < 26; f++) {
            int c0 = f * 8 + 2 * tig;
            if (c0 < STOK)     { mx0 = fmaxf(mx0, S[f][0]); mx1 = fmaxf(mx1, S[f][2]); }
            if (c0 + 1 < STOK) { mx0 = fmaxf(mx0, S[f][1]); mx1 = fmaxf(mx1, S[f][3]); }
        }
        mx0 = fmaxf(mx0, __shfl_xor_sync(0xffffffffu, mx0, 1));
        mx0 = fmaxf(mx0, __shfl_xor_sync(0xffffffffu, mx0, 2));
        mx1 = fmaxf(mx1, __shfl_xor_sync(0xffffffffu, mx1, 1));
        mx1 = fmaxf(mx1, __shfl_xor_sync(0xffffffffu, mx1, 2));

        float sum0 = 0.f, sum1 = 0.f;
        unsigned Pg[26], Pg8[26];
#pragma unroll
        for (int f = 0; f < 26; f++) {
            int c0 = f * 8 + 2 * tig;
            float e0 = (c0 < STOK)     ? __expf(S[f][0] - mx0) : 0.f;
            float e1 = (c0 + 1 < STOK) ? __expf(S[f][1] - mx0) : 0.f;
            float e2 = (c0 < STOK)     ? __expf(S[f][2] - mx1) : 0.f;
            float e3 = (c0 + 1 < STOK) ? __expf(S[f][3] - mx1) : 0.f;
            sum0 += e0 + e1;
            sum1 += e2 + e3;
            Pg[f]  = packh2(e0, e1);
            Pg8[f] = packh2(e2, e3);
        }
        sum0 += __shfl_xor_sync(0xffffffffu, sum0, 1);
        sum0 += __shfl_xor_sync(0xffffffffu, sum0, 2);
        sum1 += __shfl_xor_sync(0xffffffffu, sum1, 1);
        sum1 += __shfl_xor_sync(0xffffffffu, sum1, 2);
        float inv0 = 1.f / sum0, inv1 = 1.f / sum1;

        float O[8][4];
#pragma unroll
        for (int f = 0; f < 8; f++)
#pragma unroll
            for (int e = 0; e < 4; e++) O[f][e] = 0.f;

#pragma unroll
        for (int kt = 0; kt < 13; kt++) {
            unsigned ap[4] = {Pg[2 * kt], Pg8[2 * kt], Pg[2 * kt + 1], Pg8[2 * kt + 1]};
#pragma unroll
            for (int vd = 0; vd < 4; vd++) {
                unsigned vb[4];
                ldm4(vb, sVT + (vd * 16 + rrow) * VTS + kt * 16 + khalf);
                mma16816(O[2 * vd],     ap, vb[0], vb[2]);
                mma16816(O[2 * vd + 1], ap, vb[1], vb[3]);
            }
        }

        int q0 = qt * 16 + group;
        int q1 = q0 + 8;
#pragma unroll
        for (int nt = 0; nt < 8; nt++) {
            int col = hh * DHd + nt * 8 + 2 * tig;
            if (q0 < STOK) {
                __half2 hp = __floats2half2_rn(O[nt][0] * inv0, O[nt][1] * inv0);
                *(__half2*)(o + (size_t)(b * STOK + q0) * Dm + col) = hp;
            }
            if (q1 < STOK) {
                __half2 hp = __floats2half2_rn(O[nt][2] * inv1, O[nt][3] * inv1);
                *(__half2*)(o + (size_t)(b * STOK + q1) * Dm + col) = hp;
            }
        }
    }
}

// ---------------- host orchestration ----------------
extern "C" void kernel_launch(void* const* d_in, const int* in_sizes, int n_in,
                              void* d_out, int out_size) {
    const float* image   = (const float*)d_in[0];
    const float* gprompt = (const float*)d_in[1];
    const float* patch_w = (const float*)d_in[2];
    const float* cls_emb = (const float*)d_in[3];
    const float* pos_emb = (const float*)d_in[4];
    const float* pre_g   = (const float*)d_in[5];
    const float* pre_b   = (const float*)d_in[6];
    const float* ln1_g   = (const float*)d_in[7];
    const float* ln1_b   = (const float*)d_in[8];
    const float* qw      = (const float*)d_in[9];
    const float* qb      = (const float*)d_in[10];
    const float* kw      = (const float*)d_in[11];
    const float* kb      = (const float*)d_in[12];
    const float* vw      = (const float*)d_in[13];
    const float* vb      = (const float*)d_in[14];
    const float* ow      = (const float*)d_in[15];
    const float* ob      = (const float*)d_in[16];
    const float* ln2_g   = (const float*)d_in[17];
    const float* ln2_b   = (const float*)d_in[18];
    const float* fc1_w   = (const float*)d_in[19];
    const float* fc1_b   = (const float*)d_in[20];
    const float* fc2_w   = (const float*)d_in[21];
    const float* fc2_b   = (const float*)d_in[22];
    const float* post_g  = (const float*)d_in[23];
    const float* post_b  = (const float*)d_in[24];
    float* out = (float*)d_out;

    float *x, *feat, *bqkv;
    __half *qkvh, *ae1, *ae2, *wqkvd, *wod, *w1d, *w2d, *wpd;
    cudaGetSymbolAddress((void**)&x,    g_x);
    cudaGetSymbolAddress((void**)&feat, g_feat);
    cudaGetSymbolAddress((void**)&qkvh, g_qkvh);
    cudaGetSymbolAddress((void**)&bqkv, g_bqkv);
    cudaGetSymbolAddress((void**)&ae1,  g_ae1);
    cudaGetSymbolAddress((void**)&ae2,  g_ae2);
    cudaGetSymbolAddress((void**)&wqkvd, g_wqkv);
    cudaGetSymbolAddress((void**)&wod,  g_wo);
    cudaGetSymbolAddress((void**)&w1d,  g_w1);
    cudaGetSymbolAddress((void**)&w2d,  g_w2);
    cudaGetSymbolAddress((void**)&wpd,  g_wp);

    cudaFuncSetAttribute(attn_kernel, cudaFuncAttributeMaxDynamicSharedMemorySize, ATTN_SMEM_BYTES);
    cudaFuncSetAttribute(bgemm_kernel<0>, cudaFuncAttributeMaxDynamicSharedMemorySize, GSM);
    cudaFuncSetAttribute(bgemm_kernel<1>, cudaFuncAttributeMaxDynamicSharedMemorySize, GSM);
    cudaFuncSetAttribute(bgemm_kernel<2>, cudaFuncAttributeMaxDynamicSharedMemorySize, GSM);
    cudaFuncSetAttribute(bgemm_kernel<3>, cudaFuncAttributeMaxDynamicSharedMemorySize, GSM);

    // --- preamble; position #4 (1-based) = conv GEMM for ncu capture ---
    {
        long long n;
        n = (long long)Dm * Dm / 4;                                        // 1
        wconv_kernel<<<(unsigned)((n + 255) / 256), 256>>>(patch_w, wpd, n);
        im2col_kernel<<<(MPATCH * Dm / 2 + 255) / 256, 256>>>(image, ae1);  // 2
        bconv_qkv_kernel<<<(Lnum * NQKV + 255) / 256, 256>>>(qb, kb, vb, bqkv); // 3
        // 4: conv GEMM  <- ncu capture target
        bgemm_kernel<0><<<dim3(Dm / 128, MPATCH / 128), 256, GSM>>>(
            ae1, wpd, nullptr, nullptr, feat, Dm, Dm, MPATCH, 0);
        n = (long long)Lnum * NQKV * (Dm / 4);                              // 5
        wconv_qkv_kernel<<<(unsigned)((n + 255) / 256), 256>>>(qw, kw, vw, wqkvd);
        assemble_kernel<<<(MTOK * Dm / 4 + 255) / 256, 256>>>(feat, cls_emb, pos_emb, gprompt, x); // 6
        ln_kernel<0><<<(MTOK + 7) / 8, 256>>>(x, pre_g, pre_b, x, Dm, Dm, nullptr, 0, MTOK); // 7
        n = (long long)Lnum * Dm * Dm / 4;                                  // 8
        wconv_kernel<<<(unsigned)((n + 255) / 256), 256>>>(ow, wod, n);
        n = (long long)Lnum * FFd * Dm / 4;                                 // 9
        wconv_kernel<<<(unsigned)((n + 255) / 256), 256>>>(fc1_w, w1d, n);
        n = (long long)Lnum * Dm * FFd / 4;                                 // 10
        wconv_kernel<<<(unsigned)((n + 255) / 256), 256>>>(fc2_w, w2d, n);
    }

    dim3 g768(Dm / 128, MPAD / 128);    // (6, 103)
    dim3 gqkv(NQKV / 128, MPAD / 128);  // (18, 103)
    dim3 gff(FFd / 128, MPAD / 128);    // (24, 103)
    int lnGrid = (MTOK + 7) / 8;

    for (int l = 0; l < Lnum; l++) {
        // attention (ln1 folds the prompt replacement for l>0)
        ln_kernel<1><<<lnGrid, 256>>>(x, ln1_g + (size_t)l * Dm, ln1_b + (size_t)l * Dm,
                                      ae1, Dm, 0, gprompt, l, MTOK);
        bgemm_kernel<1><<<gqkv, 256, GSM>>>(
            ae1, wqkvd + (size_t)l * NQKV * Dm, bqkv + (size_t)l * NQKV,
            nullptr, qkvh, Dm, NQKV, MTOK, 0);
        attn_kernel<<<Bsz * Hn, 256, ATTN_SMEM_BYTES>>>(qkvh, ae1);
        bgemm_kernel<2><<<g768, 256, GSM>>>(
            ae1, wod + (size_t)l * Dm * Dm, ob + (size_t)l * Dm,
            x, x, Dm, Dm, MTOK, Dm);
        // MLP
        ln_kernel<1><<<lnGrid, 256>>>(x, ln2_g + (size_t)l * Dm, ln2_b + (size_t)l * Dm,
                                      ae1, Dm, 0, nullptr, 0, MTOK);
        bgemm_kernel<3><<<gff, 256, GSM>>>(
            ae1, w1d + (size_t)l * FFd * Dm, fc1_b + (size_t)l * FFd,
            nullptr, ae2, Dm, FFd, MTOK, 0);
        bgemm_kernel<2><<<g768, 256, GSM>>>(
            ae2, w2d + (size_t)l * Dm * FFd, fc2_b + (size_t)l * Dm,
            x, x, FFd, Dm, MTOK, Dm);
    }

    ln_kernel<0><<<(Bsz + 7) / 8, 256>>>(x, post_g, post_b, out, STOK * Dm, Dm,
                                         nullptr, 0, Bsz);
}